// round 1
// baseline (speedup 1.0000x reference)
#include <cuda_runtime.h>

#define HEADS 6
#define DIM 192
#define NTOK 49
#define HD 32
#define TABLE 169
#define THREADS 192

// smem layout (floats):
//   xs    [49*192] = 9408   (x tile; later reused as attention output [49,192])
//   qkvs  [49*576] = 28224
//   attn  [49*49]  = 2401
//   masks [49*49]  = 2401
//   rpbs  [169*6]  = 1014
//   rpis  [49*49]  = 2401 (ints)
// total = 45849 * 4 = 183396 bytes
#define SMEM_FLOATS 45849

extern "C" __global__ void __launch_bounds__(THREADS, 1)
win_attn_kernel(const float* __restrict__ x,
                const int* __restrict__ rpi_raw,   // int64 or int32, probed at runtime
                const float* __restrict__ mask,
                const float* __restrict__ qkv_w,
                const float* __restrict__ qkv_b,
                const float* __restrict__ proj_w,
                const float* __restrict__ proj_b,
                const float* __restrict__ rpb,
                float* __restrict__ out)
{
    extern __shared__ float smem[];
    float* xs    = smem;
    float* qkvs  = xs + NTOK * DIM;
    float* attn  = qkvs + NTOK * 576;
    float* masks = attn + NTOK * NTOK;
    float* rpbs  = masks + NTOK * NTOK;
    int*   rpis  = (int*)(rpbs + TABLE * HEADS);

    const int tid  = threadIdx.x;
    const int bw   = blockIdx.x;
    const int widx = bw & 63;   // window index within image (b_ = img*64 + w)

    // ---------------- Phase 1: stage inputs ----------------
    {
        const float4* xg  = (const float4*)(x + (size_t)bw * (NTOK * DIM));
        float4*       xs4 = (float4*)xs;
        #pragma unroll 4
        for (int i = tid; i < NTOK * DIM / 4; i += THREADS) xs4[i] = xg[i];

        const float* mg = mask + (size_t)widx * (NTOK * NTOK);
        for (int i = tid; i < NTOK * NTOK; i += THREADS) masks[i] = mg[i];

        // rpi dtype probe: values are in [0,169). If stored as little-endian
        // int64, every odd int32 word (high half) is 0. Random int32 data
        // having 5 specific zeros has prob ~(1/169)^5 ~ 0.
        bool is64 = (rpi_raw[1] == 0) && (rpi_raw[3] == 0) && (rpi_raw[5] == 0)
                 && (rpi_raw[7] == 0) && (rpi_raw[9] == 0);
        for (int i = tid; i < NTOK * NTOK; i += THREADS)
            rpis[i] = is64 ? rpi_raw[2 * i] : rpi_raw[i];

        for (int i = tid; i < TABLE * HEADS; i += THREADS) rpbs[i] = rpb[i];
    }
    __syncthreads();

    // ---------------- Phase 2: QKV GEMM ----------------
    // qkv[r][j] = sum_k x[r][k] * qkv_w[j][k] + qkv_b[j]
    // column-per-thread (3 columns each), 49-row register blocking.
    {
        const float4* xs4 = (const float4*)xs;
        for (int j = tid; j < 3 * DIM; j += THREADS) {
            float acc[NTOK];
            #pragma unroll
            for (int r = 0; r < NTOK; r++) acc[r] = 0.f;
            const float4* wrow = (const float4*)(qkv_w + (size_t)j * DIM);
            float4 w4 = __ldg(wrow);
            for (int kc = 0; kc < DIM / 4; kc++) {
                float4 wn;
                if (kc + 1 < DIM / 4) wn = __ldg(wrow + kc + 1);
                #pragma unroll
                for (int r = 0; r < NTOK; r++) {
                    float4 x4 = xs4[r * (DIM / 4) + kc];
                    acc[r] += x4.x * w4.x;
                    acc[r] += x4.y * w4.y;
                    acc[r] += x4.z * w4.z;
                    acc[r] += x4.w * w4.w;
                }
                w4 = wn;
            }
            float b = __ldg(qkv_b + j);
            #pragma unroll
            for (int r = 0; r < NTOK; r++)
                qkvs[r * 576 + j] = acc[r] + b;
        }
    }
    __syncthreads();

    // ---------------- Phase 3: per-head attention ----------------
    const float scale = 0.17677669529663687f;  // 32^-0.5
    float* aout = xs;  // reuse x region as [49][192] attention output
    for (int h = 0; h < HEADS; h++) {
        const int qo = h * HD;
        const int ko = DIM + h * HD;
        const int vo = 2 * DIM + h * HD;

        // scores + bias + mask
        for (int e = tid; e < NTOK * NTOK; e += THREADS) {
            int i = e / NTOK, j = e % NTOK;
            const float4* qv = (const float4*)(qkvs + i * 576 + qo);
            const float4* kv = (const float4*)(qkvs + j * 576 + ko);
            float s = 0.f;
            #pragma unroll
            for (int d4 = 0; d4 < HD / 4; d4++) {
                float4 a = qv[d4], b = kv[d4];
                s += a.x * b.x + a.y * b.y + a.z * b.z + a.w * b.w;
            }
            attn[e] = s * scale + rpbs[rpis[e] * HEADS + h] + masks[e];
        }
        __syncthreads();

        // row softmax (49 rows, one thread each)
        for (int i = tid; i < NTOK; i += THREADS) {
            float* row = attn + i * NTOK;
            float m = -1e30f;
            #pragma unroll 7
            for (int j = 0; j < NTOK; j++) m = fmaxf(m, row[j]);
            float sum = 0.f;
            #pragma unroll 7
            for (int j = 0; j < NTOK; j++) {
                float ev = __expf(row[j] - m);
                row[j] = ev;
                sum += ev;
            }
            float inv = 1.f / sum;
            #pragma unroll 7
            for (int j = 0; j < NTOK; j++) row[j] *= inv;
        }
        __syncthreads();

        // out_head = attn @ v   -> aout[r][h*32+d]
        for (int e = tid; e < NTOK * HD; e += THREADS) {
            int r = e / HD, d = e % HD;
            const float* arow = attn + r * NTOK;
            float s = 0.f;
            #pragma unroll 7
            for (int m2 = 0; m2 < NTOK; m2++)
                s += arow[m2] * qkvs[m2 * 576 + vo + d];
            aout[r * DIM + qo + d] = s;
        }
        __syncthreads();
    }

    // ---------------- Phase 4: output projection ----------------
    // out[r][c] = sum_k aout[r][k] * proj_w[c][k] + proj_b[c]
    {
        const float4* a4p = (const float4*)aout;
        float* og = out + (size_t)bw * (NTOK * DIM);
        for (int c = tid; c < DIM; c += THREADS) {  // exactly 1 column/thread
            float acc[NTOK];
            #pragma unroll
            for (int r = 0; r < NTOK; r++) acc[r] = 0.f;
            const float4* wrow = (const float4*)(proj_w + (size_t)c * DIM);
            float4 w4 = __ldg(wrow);
            for (int kc = 0; kc < DIM / 4; kc++) {
                float4 wn;
                if (kc + 1 < DIM / 4) wn = __ldg(wrow + kc + 1);
                #pragma unroll
                for (int r = 0; r < NTOK; r++) {
                    float4 a4 = a4p[r * (DIM / 4) + kc];
                    acc[r] += a4.x * w4.x;
                    acc[r] += a4.y * w4.y;
                    acc[r] += a4.z * w4.z;
                    acc[r] += a4.w * w4.w;
                }
                w4 = wn;
            }
            float b = __ldg(proj_b + c);
            #pragma unroll
            for (int r = 0; r < NTOK; r++)
                og[r * DIM + c] = acc[r] + b;
        }
    }
}

extern "C" void kernel_launch(void* const* d_in, const int* in_sizes, int n_in,
                              void* d_out, int out_size)
{
    const float* x      = (const float*)d_in[0];
    const int*   rpi    = (const int*)d_in[1];   // int64 or int32; probed in-kernel
    const float* mask   = (const float*)d_in[2];
    const float* qkv_w  = (const float*)d_in[3];
    const float* qkv_b  = (const float*)d_in[4];
    const float* proj_w = (const float*)d_in[5];
    const float* proj_b = (const float*)d_in[6];
    const float* rpb    = (const float*)d_in[7];

    size_t smem = SMEM_FLOATS * sizeof(float);
    cudaFuncSetAttribute(win_attn_kernel,
                         cudaFuncAttributeMaxDynamicSharedMemorySize, (int)smem);
    win_attn_kernel<<<4096, THREADS, smem>>>(x, rpi, mask, qkv_w, qkv_b,
                                             proj_w, proj_b, rpb, (float*)d_out);
}

// round 3
// speedup vs baseline: 1.0626x; 1.0626x over previous
#include <cuda_runtime.h>

#define HEADS 6
#define DIM 192
#define NTOK 49
#define HD 32
#define TABLE 169
#define THREADS 384

typedef unsigned long long ull;

// ---- packed fp32x2 helpers (Blackwell FFMA2 via PTX; not emitted by ptxas from C++) ----
__device__ __forceinline__ void fma2(ull& acc, ull a, ull b) {
    asm("fma.rn.f32x2 %0, %1, %2, %0;" : "+l"(acc) : "l"(a), "l"(b));
}
__device__ __forceinline__ float unpack_sum(ull a) {
    unsigned lo, hi;
    asm("mov.b64 {%0,%1}, %2;" : "=r"(lo), "=r"(hi) : "l"(a));
    return __uint_as_float(lo) + __uint_as_float(hi);
}
__device__ __forceinline__ ull dup2(float a) {
    ull r; asm("mov.b64 %0, {%1,%1};" : "=l"(r) : "f"(a)); return r;
}
__device__ __forceinline__ void unpack2(ull a, float& lo, float& hi) {
    unsigned l, h;
    asm("mov.b64 {%0,%1}, %2;" : "=r"(l), "=r"(h) : "l"(a));
    lo = __uint_as_float(l); hi = __uint_as_float(h);
}

// smem layout (floats):
//   xs    [49*192] = 9408   (x tile; reused as attention output [49,192])
//   qkvs  [49*576] = 28224
//   attn  [49*49]  = 2401
//   masks [49*49]  = 2401
//   rpbs  [169*6]  = 1014
//   rpis  [49*49]  = 2401 (ints)
#define SMEM_FLOATS 45849

extern "C" __global__ void __launch_bounds__(THREADS, 1)
win_attn_kernel(const float* __restrict__ x,
                const int* __restrict__ rpi_raw,
                const float* __restrict__ mask,
                const float* __restrict__ qkv_w,
                const float* __restrict__ qkv_b,
                const float* __restrict__ proj_w,
                const float* __restrict__ proj_b,
                const float* __restrict__ rpb,
                float* __restrict__ out)
{
    extern __shared__ float smem[];
    float* xs    = smem;
    float* qkvs  = xs + NTOK * DIM;
    float* attn  = qkvs + NTOK * 576;
    float* masks = attn + NTOK * NTOK;
    float* rpbs  = masks + NTOK * NTOK;
    int*   rpis  = (int*)(rpbs + TABLE * HEADS);

    const int tid  = threadIdx.x;
    const int bw   = blockIdx.x;
    const int widx = bw & 63;

    // ---------------- Phase 1: stage inputs ----------------
    {
        const float4* xg  = (const float4*)(x + (size_t)bw * (NTOK * DIM));
        float4*       xs4 = (float4*)xs;
        #pragma unroll 4
        for (int i = tid; i < NTOK * DIM / 4; i += THREADS) xs4[i] = xg[i];

        const float* mg = mask + (size_t)widx * (NTOK * NTOK);
        for (int i = tid; i < NTOK * NTOK; i += THREADS) masks[i] = mg[i];

        // rpi dtype probe: values in [0,169). If int64, odd 32-bit words are 0.
        bool is64 = (rpi_raw[1] == 0) && (rpi_raw[3] == 0) && (rpi_raw[5] == 0)
                 && (rpi_raw[7] == 0) && (rpi_raw[9] == 0);
        for (int i = tid; i < NTOK * NTOK; i += THREADS)
            rpis[i] = is64 ? rpi_raw[2 * i] : rpi_raw[i];

        for (int i = tid; i < TABLE * HEADS; i += THREADS) rpbs[i] = rpb[i];
    }
    __syncthreads();

    // ---------------- Phase 2: QKV GEMM (packed f32x2) ----------------
    // 1152 tasks = 576 columns x 2 row-halves (rows 0..24 / 24..48; row 24
    // computed twice, bitwise-identical value -> benign WAW). Task mapping
    // keeps every warp uniform in row-half.
    {
        const ulonglong2* xs2 = (const ulonglong2*)xs;
        for (int t = tid; t < 1152; t += THREADS) {
            int j  = t % 576;
            int rh = t / 576;
            int r0 = rh * 24;
            ull acc[25];
            #pragma unroll
            for (int r = 0; r < 25; r++) acc[r] = 0ull;
            const ulonglong2* wrow = (const ulonglong2*)(qkv_w + (size_t)j * DIM);
            for (int kc = 0; kc < DIM / 4; kc++) {
                ulonglong2 w2 = wrow[kc];
                #pragma unroll
                for (int r = 0; r < 25; r++) {
                    ulonglong2 xv = xs2[(r0 + r) * (DIM / 4) + kc];
                    fma2(acc[r], xv.x, w2.x);
                    fma2(acc[r], xv.y, w2.y);
                }
            }
            float b = __ldg(qkv_b + j);
            #pragma unroll
            for (int r = 0; r < 25; r++)
                qkvs[(r0 + r) * 576 + j] = unpack_sum(acc[r]) + b;
        }
    }
    __syncthreads();

    // ---------------- Phase 3: per-head attention ----------------
    const float scale = 0.17677669529663687f;  // 32^-0.5
    float* aout = xs;  // reuse x region as [49][192]
    for (int h = 0; h < HEADS; h++) {
        const int qo = h * HD;
        const int ko = DIM + h * HD;
        const int vo = 2 * DIM + h * HD;

        // scores + bias + mask (packed dot over HD=32 floats = 8 ulonglong2)
        for (int e = tid; e < NTOK * NTOK; e += THREADS) {
            int i = e / NTOK, jj = e - i * NTOK;
            const ulonglong2* qv = (const ulonglong2*)(qkvs + i * 576 + qo);
            const ulonglong2* kv = (const ulonglong2*)(qkvs + jj * 576 + ko);
            ull a0 = 0ull, a1 = 0ull;
            #pragma unroll
            for (int p = 0; p < HD / 4; p++) {   // FIX: ulonglong2 = 4 floats
                ulonglong2 q2 = qv[p], k2 = kv[p];
                fma2(a0, q2.x, k2.x);
                fma2(a1, q2.y, k2.y);
            }
            attn[e] = (unpack_sum(a0) + unpack_sum(a1)) * scale
                    + rpbs[rpis[e] * HEADS + h] + masks[e];
        }
        __syncthreads();

        // row softmax (one thread per row)
        if (tid < NTOK) {
            float* row = attn + tid * NTOK;
            float m = -1e30f;
            #pragma unroll 7
            for (int j = 0; j < NTOK; j++) m = fmaxf(m, row[j]);
            float sum = 0.f;
            #pragma unroll 7
            for (int j = 0; j < NTOK; j++) {
                float ev = __expf(row[j] - m);
                row[j] = ev;
                sum += ev;
            }
            float inv = 1.f / sum;
            #pragma unroll 7
            for (int j = 0; j < NTOK; j++) row[j] *= inv;
        }
        __syncthreads();

        // out_head = attn @ v : 392 tasks (49 rows x 8 d-pairs), each task
        // produces packed outputs (d,d+1) and (d+16,d+17).
        for (int t = tid; t < NTOK * 8; t += THREADS) {
            int r = t >> 3, dp = t & 7;
            int d = dp * 2;
            const float* arow  = attn + r * NTOK;
            const ull* v0 = (const ull*)(qkvs + vo + d);
            const ull* v1 = (const ull*)(qkvs + vo + d + 16);
            ull acc0 = 0ull, acc1 = 0ull;
            #pragma unroll 7
            for (int m2 = 0; m2 < NTOK; m2++) {
                ull a2 = dup2(arow[m2]);
                fma2(acc0, a2, v0[m2 * 288]);
                fma2(acc1, a2, v1[m2 * 288]);
            }
            float l0, h0, l1, h1;
            unpack2(acc0, l0, h0);
            unpack2(acc1, l1, h1);
            float* ar = aout + r * DIM + qo;
            ar[d] = l0; ar[d + 1] = h0;
            ar[d + 16] = l1; ar[d + 17] = h1;
        }
        __syncthreads();
    }

    // ---------------- Phase 4: output projection (packed f32x2) ----------------
    // 384 tasks = 192 cols x 2 row-halves, exactly one per thread.
    {
        const ulonglong2* a2p = (const ulonglong2*)aout;
        float* og = out + (size_t)bw * (NTOK * DIM);
        int c  = tid % 192;
        int rh = tid / 192;
        int r0 = rh * 24;
        ull acc[25];
        #pragma unroll
        for (int r = 0; r < 25; r++) acc[r] = 0ull;
        const ulonglong2* wrow = (const ulonglong2*)(proj_w + (size_t)c * DIM);
        for (int kc = 0; kc < DIM / 4; kc++) {
            ulonglong2 w2 = wrow[kc];
            #pragma unroll
            for (int r = 0; r < 25; r++) {
                ulonglong2 av = a2p[(r0 + r) * (DIM / 4) + kc];
                fma2(acc[r], av.x, w2.x);
                fma2(acc[r], av.y, w2.y);
            }
        }
        float b = __ldg(proj_b + c);
        #pragma unroll
        for (int r = 0; r < 25; r++)
            og[(r0 + r) * DIM + c] = unpack_sum(acc[r]) + b;
    }
}

extern "C" void kernel_launch(void* const* d_in, const int* in_sizes, int n_in,
                              void* d_out, int out_size)
{
    const float* x      = (const float*)d_in[0];
    const int*   rpi    = (const int*)d_in[1];
    const float* mask   = (const float*)d_in[2];
    const float* qkv_w  = (const float*)d_in[3];
    const float* qkv_b  = (const float*)d_in[4];
    const float* proj_w = (const float*)d_in[5];
    const float* proj_b = (const float*)d_in[6];
    const float* rpb    = (const float*)d_in[7];

    size_t smem = SMEM_FLOATS * sizeof(float);
    cudaFuncSetAttribute(win_attn_kernel,
                         cudaFuncAttributeMaxDynamicSharedMemorySize, (int)smem);
    win_attn_kernel<<<4096, THREADS, smem>>>(x, rpi, mask, qkv_w, qkv_b,
                                             proj_w, proj_b, rpb, (float*)d_out);
}

// round 4
// speedup vs baseline: 2.0622x; 1.9407x over previous
#include <cuda_runtime.h>

#define HEADS 6
#define DIM 192
#define NTOK 49
#define HD 32
#define TABLE 169
#define THREADS 384
#define XS_STRIDE 196      // floats (= 49 float4), 196 % 32 = 4 -> conflict-free-ish
#define QS_STRIDE 580      // floats, 580 % 32 = 4

typedef unsigned long long ull;

// ---- packed fp32x2 helpers (Blackwell FFMA2 via PTX) ----
__device__ __forceinline__ void fma2(ull& acc, ull a, ull b) {
    asm("fma.rn.f32x2 %0, %1, %2, %0;" : "+l"(acc) : "l"(a), "l"(b));
}
__device__ __forceinline__ float unpack_sum(ull a) {
    unsigned lo, hi;
    asm("mov.b64 {%0,%1}, %2;" : "=r"(lo), "=r"(hi) : "l"(a));
    return __uint_as_float(lo) + __uint_as_float(hi);
}
__device__ __forceinline__ ull dup2(float a) {
    ull r; asm("mov.b64 %0, {%1,%1};" : "=l"(r) : "f"(a)); return r;
}
__device__ __forceinline__ void unpack2(ull a, float& lo, float& hi) {
    unsigned l, h;
    asm("mov.b64 {%0,%1}, %2;" : "=r"(l), "=r"(h) : "l"(a));
    lo = __uint_as_float(l); hi = __uint_as_float(h);
}

// transposed weights, [k][j] layout, 16B aligned for vector loads
__device__ __align__(16) float g_wqkvT[DIM * 3 * DIM];   // 192 x 576
__device__ __align__(16) float g_wprojT[DIM * DIM];      // 192 x 192

__global__ void transpose_w(const float* __restrict__ qkv_w,
                            const float* __restrict__ proj_w)
{
    int idx = blockIdx.x * blockDim.x + threadIdx.x;
    const int n1 = 3 * DIM * DIM;      // 110592
    if (idx < n1) {
        int j = idx / DIM, k = idx - j * DIM;
        g_wqkvT[k * (3 * DIM) + j] = qkv_w[idx];
    } else if (idx < n1 + DIM * DIM) {
        int i2 = idx - n1;
        int j = i2 / DIM, k = i2 - j * DIM;
        g_wprojT[k * DIM + j] = proj_w[i2];
    }
}

// smem floats: xs 49*196=9604 | qkvs 49*580=28420 | attn 2401 | masks 2401 |
//              rpbs 1014 | rpis 2401(int)   total 46241 *4B = 184964 B
#define SMEM_FLOATS 46241

extern "C" __global__ void __launch_bounds__(THREADS, 1)
win_attn_kernel(const float* __restrict__ x,
                const int* __restrict__ rpi_raw,
                const float* __restrict__ mask,
                const float* __restrict__ qkv_b,
                const float* __restrict__ proj_b,
                const float* __restrict__ rpb,
                float* __restrict__ out)
{
    extern __shared__ float smem[];
    float* xs    = smem;                          // [49][196] (data in first 192)
    float* qkvs  = xs + NTOK * XS_STRIDE;         // [49][580] (data in first 576)
    float* attn  = qkvs + NTOK * QS_STRIDE;
    float* masks = attn + NTOK * NTOK;
    float* rpbs  = masks + NTOK * NTOK;
    int*   rpis  = (int*)(rpbs + TABLE * HEADS);

    const int tid  = threadIdx.x;
    const int bw   = blockIdx.x;
    const int widx = bw & 63;
    const int lane = tid & 31, warp = tid >> 5;
    const int rq = lane >> 2;      // 0..7  (row group)
    const int jq = lane & 3;       // 0..3  (col group)

    // ---------------- Phase 1: stage inputs (padded xs) ----------------
    {
        const float4* xg  = (const float4*)(x + (size_t)bw * (NTOK * DIM));
        float4*       xs4 = (float4*)xs;
        #pragma unroll 4
        for (int i = tid; i < NTOK * DIM / 4; i += THREADS) {
            int r = i / 48, c4 = i - r * 48;
            xs4[r * 49 + c4] = xg[i];
        }
        const float* mg = mask + (size_t)widx * (NTOK * NTOK);
        for (int i = tid; i < NTOK * NTOK; i += THREADS) masks[i] = mg[i];

        bool is64 = (rpi_raw[1] == 0) && (rpi_raw[3] == 0) && (rpi_raw[5] == 0)
                 && (rpi_raw[7] == 0) && (rpi_raw[9] == 0);
        for (int i = tid; i < NTOK * NTOK; i += THREADS)
            rpis[i] = is64 ? rpi_raw[2 * i] : rpi_raw[i];

        for (int i = tid; i < TABLE * HEADS; i += THREADS) rpbs[i] = rpb[i];
    }
    __syncthreads();

    // ---------------- Phase 2: QKV GEMM ----------------
    // warp owns 48 cols (12 float4-blocks); thread: 3 blocks (jq,jq+4,jq+8) x 4 rows.
    // Rows: pass0 = rq+8i (0..31), pass1 = 17+rq+8i (17..48; overlap rows recomputed
    // identically by the same warp -> benign).
    {
        const float4* xs4 = (const float4*)xs;
        const ulonglong2* wT2 = (const ulonglong2*)g_wqkvT;  // row = 144 u2
        const int fb0 = warp * 12 + jq;
        float2 bias[6];
        #pragma unroll
        for (int s = 0; s < 3; s++)
            #pragma unroll
            for (int h = 0; h < 2; h++)
                bias[2 * s + h] = *(const float2*)(qkv_b + 4 * (fb0 + 4 * s) + 2 * h);

        #pragma unroll
        for (int pass = 0; pass < 2; pass++) {
            const int rbase = pass ? 17 : 0;
            ull acc[4][6];
            #pragma unroll
            for (int i = 0; i < 4; i++)
                #pragma unroll
                for (int c = 0; c < 6; c++) acc[i][c] = 0ull;

            for (int kc = 0; kc < DIM; kc += 8) {
                float4 xq[4][2];
                #pragma unroll
                for (int i = 0; i < 4; i++) {
                    int r = rbase + rq + 8 * i;
                    xq[i][0] = xs4[r * 49 + (kc >> 2)];
                    xq[i][1] = xs4[r * 49 + (kc >> 2) + 1];
                }
                #pragma unroll
                for (int kk = 0; kk < 8; kk++) {
                    int krow = (kc + kk) * 144;
                    ulonglong2 wa = wT2[krow + fb0];
                    ulonglong2 wb = wT2[krow + fb0 + 4];
                    ulonglong2 wc = wT2[krow + fb0 + 8];
                    #pragma unroll
                    for (int i = 0; i < 4; i++) {
                        float xv;
                        if (kk == 0) xv = xq[i][0].x; else if (kk == 1) xv = xq[i][0].y;
                        else if (kk == 2) xv = xq[i][0].z; else if (kk == 3) xv = xq[i][0].w;
                        else if (kk == 4) xv = xq[i][1].x; else if (kk == 5) xv = xq[i][1].y;
                        else if (kk == 6) xv = xq[i][1].z; else xv = xq[i][1].w;
                        ull xd = dup2(xv);
                        fma2(acc[i][0], xd, wa.x);
                        fma2(acc[i][1], xd, wa.y);
                        fma2(acc[i][2], xd, wb.x);
                        fma2(acc[i][3], xd, wb.y);
                        fma2(acc[i][4], xd, wc.x);
                        fma2(acc[i][5], xd, wc.y);
                    }
                }
            }
            #pragma unroll
            for (int i = 0; i < 4; i++) {
                int r = rbase + rq + 8 * i;
                #pragma unroll
                for (int s = 0; s < 3; s++) {
                    #pragma unroll
                    for (int h = 0; h < 2; h++) {
                        int c = 4 * (fb0 + 4 * s) + 2 * h;
                        float lo, hi; unpack2(acc[i][2 * s + h], lo, hi);
                        float2 bv = bias[2 * s + h];
                        *(float2*)(qkvs + r * QS_STRIDE + c) =
                            make_float2(lo + bv.x, hi + bv.y);
                    }
                }
            }
        }
    }
    __syncthreads();

    // ---------------- Phase 3: per-head attention ----------------
    const float scale = 0.17677669529663687f;  // 32^-0.5
    float* aout = xs;  // reuse x region, [49][XS_STRIDE]
    for (int h = 0; h < HEADS; h++) {
        const int qo = h * HD;
        const int ko = DIM + h * HD;
        const int vo = 2 * DIM + h * HD;

        for (int e = tid; e < NTOK * NTOK; e += THREADS) {
            int i = e / NTOK, jj = e - i * NTOK;
            const ulonglong2* qv = (const ulonglong2*)(qkvs + i * QS_STRIDE + qo);
            const ulonglong2* kv = (const ulonglong2*)(qkvs + jj * QS_STRIDE + ko);
            ull a0 = 0ull, a1 = 0ull;
            #pragma unroll
            for (int p = 0; p < HD / 4; p++) {
                ulonglong2 q2 = qv[p], k2 = kv[p];
                fma2(a0, q2.x, k2.x);
                fma2(a1, q2.y, k2.y);
            }
            attn[e] = (unpack_sum(a0) + unpack_sum(a1)) * scale
                    + rpbs[rpis[e] * HEADS + h] + masks[e];
        }
        __syncthreads();

        if (tid < NTOK) {
            float* row = attn + tid * NTOK;
            float m = -1e30f;
            #pragma unroll 7
            for (int j = 0; j < NTOK; j++) m = fmaxf(m, row[j]);
            float sum = 0.f;
            #pragma unroll 7
            for (int j = 0; j < NTOK; j++) {
                float ev = __expf(row[j] - m);
                row[j] = ev;
                sum += ev;
            }
            float inv = 1.f / sum;
            #pragma unroll 7
            for (int j = 0; j < NTOK; j++) row[j] *= inv;
        }
        __syncthreads();

        for (int t = tid; t < NTOK * 8; t += THREADS) {
            int r = t >> 3, dp = t & 7;
            int d = dp * 2;
            const float* arow = attn + r * NTOK;
            const ull* v0 = (const ull*)(qkvs + vo + d);
            const ull* v1 = (const ull*)(qkvs + vo + d + 16);
            ull acc0 = 0ull, acc1 = 0ull;
            #pragma unroll 7
            for (int m2 = 0; m2 < NTOK; m2++) {
                ull a2 = dup2(arow[m2]);
                fma2(acc0, a2, v0[m2 * (QS_STRIDE / 2)]);
                fma2(acc1, a2, v1[m2 * (QS_STRIDE / 2)]);
            }
            float l0, h0, l1, h1;
            unpack2(acc0, l0, h0);
            unpack2(acc1, l1, h1);
            float* ar = aout + r * XS_STRIDE + qo;
            ar[d] = l0; ar[d + 1] = h0;
            ar[d + 16] = l1; ar[d + 17] = h1;
        }
        __syncthreads();
    }

    // ---------------- Phase 4: output projection ----------------
    // warp owns 16 cols (4 blocks); thread: 1 block (fbp) x 4 rows, 2 passes.
    {
        const float4* a4p = (const float4*)aout;
        const ulonglong2* pT2 = (const ulonglong2*)g_wprojT;  // row = 48 u2
        float* og = out + (size_t)bw * (NTOK * DIM);
        const int fbp = warp * 4 + jq;          // 0..47
        const int c0 = fbp * 4;
        float4 bias = *(const float4*)(proj_b + c0);

        #pragma unroll
        for (int pass = 0; pass < 2; pass++) {
            const int rbase = pass ? 17 : 0;
            ull acc[4][2];
            #pragma unroll
            for (int i = 0; i < 4; i++) { acc[i][0] = 0ull; acc[i][1] = 0ull; }

            for (int kc = 0; kc < DIM; kc += 8) {
                float4 xq[4][2];
                #pragma unroll
                for (int i = 0; i < 4; i++) {
                    int r = rbase + rq + 8 * i;
                    xq[i][0] = a4p[r * 49 + (kc >> 2)];
                    xq[i][1] = a4p[r * 49 + (kc >> 2) + 1];
                }
                #pragma unroll
                for (int kk = 0; kk < 8; kk++) {
                    ulonglong2 w2 = pT2[(kc + kk) * 48 + fbp];
                    #pragma unroll
                    for (int i = 0; i < 4; i++) {
                        float xv;
                        if (kk == 0) xv = xq[i][0].x; else if (kk == 1) xv = xq[i][0].y;
                        else if (kk == 2) xv = xq[i][0].z; else if (kk == 3) xv = xq[i][0].w;
                        else if (kk == 4) xv = xq[i][1].x; else if (kk == 5) xv = xq[i][1].y;
                        else if (kk == 6) xv = xq[i][1].z; else xv = xq[i][1].w;
                        ull xd = dup2(xv);
                        fma2(acc[i][0], xd, w2.x);
                        fma2(acc[i][1], xd, w2.y);
                    }
                }
            }
            #pragma unroll
            for (int i = 0; i < 4; i++) {
                int r = rbase + rq + 8 * i;
                float l0, h0, l1, h1;
                unpack2(acc[i][0], l0, h0);
                unpack2(acc[i][1], l1, h1);
                *(float4*)(og + r * DIM + c0) =
                    make_float4(l0 + bias.x, h0 + bias.y, l1 + bias.z, h1 + bias.w);
            }
        }
    }
}

extern "C" void kernel_launch(void* const* d_in, const int* in_sizes, int n_in,
                              void* d_out, int out_size)
{
    const float* x      = (const float*)d_in[0];
    const int*   rpi    = (const int*)d_in[1];
    const float* mask   = (const float*)d_in[2];
    const float* qkv_w  = (const float*)d_in[3];
    const float* qkv_b  = (const float*)d_in[4];
    const float* proj_w = (const float*)d_in[5];
    const float* proj_b = (const float*)d_in[6];
    const float* rpb    = (const float*)d_in[7];

    transpose_w<<<(3 * DIM * DIM + DIM * DIM + 383) / 384, 384>>>(qkv_w, proj_w);

    size_t smem = SMEM_FLOATS * sizeof(float);
    cudaFuncSetAttribute(win_attn_kernel,
                         cudaFuncAttributeMaxDynamicSharedMemorySize, (int)smem);
    win_attn_kernel<<<4096, THREADS, smem>>>(x, rpi, mask, qkv_b,
                                             proj_b, rpb, (float*)d_out);
}

// round 5
// speedup vs baseline: 2.6533x; 1.2866x over previous
#include <cuda_runtime.h>

#define HEADS 6
#define DIM 192
#define NTOK 49
#define HD 32
#define TABLE 169
#define THREADS 384
#define XS_STRIDE 196
#define QS_STRIDE 580

typedef unsigned long long ull;

__device__ __forceinline__ void fma2(ull& acc, ull a, ull b) {
    asm("fma.rn.f32x2 %0, %1, %2, %0;" : "+l"(acc) : "l"(a), "l"(b));
}
__device__ __forceinline__ float unpack_sum(ull a) {
    unsigned lo, hi;
    asm("mov.b64 {%0,%1}, %2;" : "=r"(lo), "=r"(hi) : "l"(a));
    return __uint_as_float(lo) + __uint_as_float(hi);
}
__device__ __forceinline__ ull dup2(float a) {
    ull r; asm("mov.b64 %0, {%1,%1};" : "=l"(r) : "f"(a)); return r;
}
__device__ __forceinline__ void unpack2(ull a, float& lo, float& hi) {
    unsigned l, h;
    asm("mov.b64 {%0,%1}, %2;" : "=r"(l), "=r"(h) : "l"(a));
    lo = __uint_as_float(l); hi = __uint_as_float(h);
}

__device__ __align__(16) float g_wqkvT[DIM * 3 * DIM];   // [k][j] 192x576
__device__ __align__(16) float g_wprojT[DIM * DIM];      // [k][j] 192x192

__global__ void transpose_w(const float* __restrict__ qkv_w,
                            const float* __restrict__ proj_w)
{
    int idx = blockIdx.x * blockDim.x + threadIdx.x;
    const int n1 = 3 * DIM * DIM;
    if (idx < n1) {
        int j = idx / DIM, k = idx - j * DIM;
        g_wqkvT[k * (3 * DIM) + j] = qkv_w[idx];
    } else if (idx < n1 + DIM * DIM) {
        int i2 = idx - n1;
        int j = i2 / DIM, k = i2 - j * DIM;
        g_wprojT[k * DIM + j] = proj_w[i2];
    }
}

// smem floats: xs 49*196=9604 | qkvs 49*580=28420 | masks 2401 | rpbs 1014 | rpis 2401
#define SMEM_FLOATS 43840

extern "C" __global__ void __launch_bounds__(THREADS, 1)
win_attn_kernel(const float* __restrict__ x,
                const int* __restrict__ rpi_raw,
                const float* __restrict__ mask,
                const float* __restrict__ qkv_b,
                const float* __restrict__ proj_b,
                const float* __restrict__ rpb,
                float* __restrict__ out)
{
    extern __shared__ float smem[];
    float* xs    = smem;                          // [49][196]
    float* qkvs  = xs + NTOK * XS_STRIDE;         // [49][580]
    float* masks = qkvs + NTOK * QS_STRIDE;
    float* rpbs  = masks + NTOK * NTOK;
    int*   rpis  = (int*)(rpbs + TABLE * HEADS);

    const int tid  = threadIdx.x;
    const int bw   = blockIdx.x;
    const int widx = bw & 63;
    const int lane = tid & 31, warp = tid >> 5;
    const int rq = lane >> 2;
    const int jq = lane & 3;

    // ---------------- Phase 1: stage inputs ----------------
    {
        const float4* xg  = (const float4*)(x + (size_t)bw * (NTOK * DIM));
        float4*       xs4 = (float4*)xs;
        #pragma unroll 4
        for (int i = tid; i < NTOK * DIM / 4; i += THREADS) {
            int r = i / 48, c4 = i - r * 48;
            xs4[r * 49 + c4] = xg[i];
        }
        const float* mg = mask + (size_t)widx * (NTOK * NTOK);
        for (int i = tid; i < NTOK * NTOK; i += THREADS) masks[i] = mg[i];

        bool is64 = (rpi_raw[1] == 0) && (rpi_raw[3] == 0) && (rpi_raw[5] == 0)
                 && (rpi_raw[7] == 0) && (rpi_raw[9] == 0);
        for (int i = tid; i < NTOK * NTOK; i += THREADS)
            rpis[i] = is64 ? rpi_raw[2 * i] : rpi_raw[i];

        for (int i = tid; i < TABLE * HEADS; i += THREADS) rpbs[i] = rpb[i];
    }
    __syncthreads();

    // ---------------- Phase 2: QKV GEMM (unchanged from R4) ----------------
    {
        const float4* xs4 = (const float4*)xs;
        const ulonglong2* wT2 = (const ulonglong2*)g_wqkvT;
        const int fb0 = warp * 12 + jq;
        float2 bias[6];
        #pragma unroll
        for (int s = 0; s < 3; s++)
            #pragma unroll
            for (int h = 0; h < 2; h++)
                bias[2 * s + h] = *(const float2*)(qkv_b + 4 * (fb0 + 4 * s) + 2 * h);

        #pragma unroll
        for (int pass = 0; pass < 2; pass++) {
            const int rbase = pass ? 17 : 0;
            ull acc[4][6];
            #pragma unroll
            for (int i = 0; i < 4; i++)
                #pragma unroll
                for (int c = 0; c < 6; c++) acc[i][c] = 0ull;

            for (int kc = 0; kc < DIM; kc += 8) {
                float4 xq[4][2];
                #pragma unroll
                for (int i = 0; i < 4; i++) {
                    int r = rbase + rq + 8 * i;
                    xq[i][0] = xs4[r * 49 + (kc >> 2)];
                    xq[i][1] = xs4[r * 49 + (kc >> 2) + 1];
                }
                #pragma unroll
                for (int kk = 0; kk < 8; kk++) {
                    int krow = (kc + kk) * 144;
                    ulonglong2 wa = wT2[krow + fb0];
                    ulonglong2 wb = wT2[krow + fb0 + 4];
                    ulonglong2 wc = wT2[krow + fb0 + 8];
                    #pragma unroll
                    for (int i = 0; i < 4; i++) {
                        float xv;
                        if (kk == 0) xv = xq[i][0].x; else if (kk == 1) xv = xq[i][0].y;
                        else if (kk == 2) xv = xq[i][0].z; else if (kk == 3) xv = xq[i][0].w;
                        else if (kk == 4) xv = xq[i][1].x; else if (kk == 5) xv = xq[i][1].y;
                        else if (kk == 6) xv = xq[i][1].z; else xv = xq[i][1].w;
                        ull xd = dup2(xv);
                        fma2(acc[i][0], xd, wa.x);
                        fma2(acc[i][1], xd, wa.y);
                        fma2(acc[i][2], xd, wb.x);
                        fma2(acc[i][3], xd, wb.y);
                        fma2(acc[i][4], xd, wc.x);
                        fma2(acc[i][5], xd, wc.y);
                    }
                }
            }
            #pragma unroll
            for (int i = 0; i < 4; i++) {
                int r = rbase + rq + 8 * i;
                #pragma unroll
                for (int s = 0; s < 3; s++) {
                    #pragma unroll
                    for (int h = 0; h < 2; h++) {
                        int c = 4 * (fb0 + 4 * s) + 2 * h;
                        float lo, hi; unpack2(acc[i][2 * s + h], lo, hi);
                        float2 bv = bias[2 * s + h];
                        *(float2*)(qkvs + r * QS_STRIDE + c) =
                            make_float2(lo + bv.x, hi + bv.y);
                    }
                }
            }
        }
    }
    __syncthreads();

    // ---------------- Phase 3: warp-per-head register attention ----------------
    // warp w: head = w>>1, row-half = w&1 (rows 0..24 / 25..48). Lane = query row.
    // q row + score row live in registers. Zero internal barriers.
    float* aout = xs;  // reuse as [49][XS_STRIDE]
    {
        const float scale = 0.17677669529663687f;  // 32^-0.5
        const int h    = warp >> 1;
        const int half = warp & 1;
        const int nrows = half ? 24 : 25;
        const bool act = lane < nrows;
        const int i = half * 25 + (act ? lane : 0);
        const int qo = h * HD, ko = DIM + h * HD, vo = 2 * DIM + h * HD;

        // q row -> registers (32 floats as 16 packed pairs)
        ull q2[16];
        {
            const ulonglong2* qv = (const ulonglong2*)(qkvs + i * QS_STRIDE + qo);
            #pragma unroll
            for (int p = 0; p < 8; p++) {
                ulonglong2 t = qv[p];
                q2[2 * p] = t.x; q2[2 * p + 1] = t.y;
            }
        }

        const int*   rp = rpis + i * NTOK;
        const float* mk = masks + i * NTOK;

        float srow[NTOK];
        #pragma unroll
        for (int j = 0; j < NTOK; j++) {
            const ulonglong2* kv = (const ulonglong2*)(qkvs + j * QS_STRIDE + ko);
            ull a0 = 0ull, a1 = 0ull;
            #pragma unroll
            for (int p = 0; p < 8; p++) {
                ulonglong2 k2 = kv[p];           // warp-uniform -> broadcast
                fma2(a0, q2[2 * p], k2.x);
                fma2(a1, q2[2 * p + 1], k2.y);
            }
            srow[j] = (unpack_sum(a0) + unpack_sum(a1)) * scale
                    + rpbs[rp[j] * HEADS + h] + mk[j];
        }

        // register softmax
        float m = -1e30f;
        #pragma unroll
        for (int j = 0; j < NTOK; j++) m = fmaxf(m, srow[j]);
        float sum = 0.f;
        #pragma unroll
        for (int j = 0; j < NTOK; j++) {
            float ev = __expf(srow[j] - m);
            srow[j] = ev;
            sum += ev;
        }
        float inv = 1.f / sum;
        #pragma unroll
        for (int j = 0; j < NTOK; j++) srow[j] *= inv;

        // AV: acc 32 floats in 16 packed pairs
        ull acc[16];
        #pragma unroll
        for (int p = 0; p < 16; p++) acc[p] = 0ull;
        #pragma unroll
        for (int j = 0; j < NTOK; j++) {
            const ulonglong2* vv = (const ulonglong2*)(qkvs + j * QS_STRIDE + vo);
            ull aj = dup2(srow[j]);
            #pragma unroll
            for (int p = 0; p < 8; p++) {
                ulonglong2 v2 = vv[p];           // warp-uniform -> broadcast
                fma2(acc[2 * p], aj, v2.x);
                fma2(acc[2 * p + 1], aj, v2.y);
            }
        }
        if (act) {
            float* ar = aout + i * XS_STRIDE + qo;
            #pragma unroll
            for (int p = 0; p < 8; p++) {
                float l0, h0, l1, h1;
                unpack2(acc[2 * p], l0, h0);
                unpack2(acc[2 * p + 1], l1, h1);
                *(float4*)(ar + 4 * p) = make_float4(l0, h0, l1, h1);
            }
        }
    }
    __syncthreads();

    // ---------------- Phase 4: output projection (unchanged from R4) ----------------
    {
        const float4* a4p = (const float4*)aout;
        const ulonglong2* pT2 = (const ulonglong2*)g_wprojT;
        float* og = out + (size_t)bw * (NTOK * DIM);
        const int fbp = warp * 4 + jq;
        const int c0 = fbp * 4;
        float4 bias = *(const float4*)(proj_b + c0);

        #pragma unroll
        for (int pass = 0; pass < 2; pass++) {
            const int rbase = pass ? 17 : 0;
            ull acc[4][2];
            #pragma unroll
            for (int i = 0; i < 4; i++) { acc[i][0] = 0ull; acc[i][1] = 0ull; }

            for (int kc = 0; kc < DIM; kc += 8) {
                float4 xq[4][2];
                #pragma unroll
                for (int i = 0; i < 4; i++) {
                    int r = rbase + rq + 8 * i;
                    xq[i][0] = a4p[r * 49 + (kc >> 2)];
                    xq[i][1] = a4p[r * 49 + (kc >> 2) + 1];
                }
                #pragma unroll
                for (int kk = 0; kk < 8; kk++) {
                    ulonglong2 w2 = pT2[(kc + kk) * 48 + fbp];
                    #pragma unroll
                    for (int i = 0; i < 4; i++) {
                        float xv;
                        if (kk == 0) xv = xq[i][0].x; else if (kk == 1) xv = xq[i][0].y;
                        else if (kk == 2) xv = xq[i][0].z; else if (kk == 3) xv = xq[i][0].w;
                        else if (kk == 4) xv = xq[i][1].x; else if (kk == 5) xv = xq[i][1].y;
                        else if (kk == 6) xv = xq[i][1].z; else xv = xq[i][1].w;
                        ull xd = dup2(xv);
                        fma2(acc[i][0], xd, w2.x);
                        fma2(acc[i][1], xd, w2.y);
                    }
                }
            }
            #pragma unroll
            for (int i = 0; i < 4; i++) {
                int r = rbase + rq + 8 * i;
                float l0, h0, l1, h1;
                unpack2(acc[i][0], l0, h0);
                unpack2(acc[i][1], l1, h1);
                *(float4*)(og + r * DIM + c0) =
                    make_float4(l0 + bias.x, h0 + bias.y, l1 + bias.z, h1 + bias.w);
            }
        }
    }
}

extern "C" void kernel_launch(void* const* d_in, const int* in_sizes, int n_in,
                              void* d_out, int out_size)
{
    const float* x      = (const float*)d_in[0];
    const int*   rpi    = (const int*)d_in[1];
    const float* mask   = (const float*)d_in[2];
    const float* qkv_w  = (const float*)d_in[3];
    const float* qkv_b  = (const float*)d_in[4];
    const float* proj_w = (const float*)d_in[5];
    const float* proj_b = (const float*)d_in[6];
    const float* rpb    = (const float*)d_in[7];

    transpose_w<<<(3 * DIM * DIM + DIM * DIM + 383) / 384, 384>>>(qkv_w, proj_w);

    size_t smem = SMEM_FLOATS * sizeof(float);
    cudaFuncSetAttribute(win_attn_kernel,
                         cudaFuncAttributeMaxDynamicSharedMemorySize, (int)smem);
    win_attn_kernel<<<4096, THREADS, smem>>>(x, rpi, mask, qkv_b,
                                             proj_b, rpb, (float*)d_out);
}

// round 7
// speedup vs baseline: 5.2033x; 1.9611x over previous
#include <cuda_runtime.h>
#include <cuda_bf16.h>
#include <cstdint>

#define HEADS 6
#define DIM 192
#define NTOK 49
#define TABLE 169
#define THREADS 384
#define QS_STRIDE 580
#define XS_STRIDE 200       // bf16 elems; 400B rows -> ldmatrix conflict-free

// smem byte offsets
#define SM_XHI   0          // [64][200] bf16 = 25600
#define SM_XLO   25600      // 25600
#define SM_QKVS  51200      // [49][580] f32 = 113680
#define SM_MASK  164880     // 9604
#define SM_RPB   174484     // 4056
#define SM_RPI   178540     // 9604
#define SM_TOTAL 188144

typedef unsigned long long ull;

// ---- packed fp32x2 helpers (attention phase) ----
__device__ __forceinline__ void fma2(ull& acc, ull a, ull b) {
    asm("fma.rn.f32x2 %0, %1, %2, %0;" : "+l"(acc) : "l"(a), "l"(b));
}
__device__ __forceinline__ float unpack_sum(ull a) {
    unsigned lo, hi;
    asm("mov.b64 {%0,%1}, %2;" : "=r"(lo), "=r"(hi) : "l"(a));
    return __uint_as_float(lo) + __uint_as_float(hi);
}
__device__ __forceinline__ ull dup2(float a) {
    ull r; asm("mov.b64 %0, {%1,%1};" : "=l"(r) : "f"(a)); return r;
}
__device__ __forceinline__ void unpack2(ull a, float& lo, float& hi) {
    unsigned l, h;
    asm("mov.b64 {%0,%1}, %2;" : "=r"(l), "=r"(h) : "l"(a));
    lo = __uint_as_float(l); hi = __uint_as_float(h);
}

// ---- tensor-core primitives (arch-agnostic PTX, sm_80+) ----
__device__ __forceinline__ uint32_t smem_u32(const void* p) {
    uint32_t a;
    asm("{ .reg .u64 t; cvta.to.shared.u64 t, %1; cvt.u32.u64 %0, t; }" : "=r"(a) : "l"(p));
    return a;
}
__device__ __forceinline__ void ldm4(uint32_t* r, uint32_t addr) {
    asm volatile("ldmatrix.sync.aligned.m8n8.x4.shared.b16 {%0,%1,%2,%3}, [%4];"
        : "=r"(r[0]), "=r"(r[1]), "=r"(r[2]), "=r"(r[3]) : "r"(addr));
}
__device__ __forceinline__ void mma16816(float* c, const uint32_t* a, uint2 b) {
    asm volatile("mma.sync.aligned.m16n8k16.row.col.f32.bf16.bf16.f32 "
        "{%0,%1,%2,%3},{%4,%5,%6,%7},{%8,%9},{%0,%1,%2,%3};"
        : "+f"(c[0]), "+f"(c[1]), "+f"(c[2]), "+f"(c[3])
        : "r"(a[0]), "r"(a[1]), "r"(a[2]), "r"(a[3]), "r"(b.x), "r"(b.y));
}

// ---- pre-packed B fragments (fragment-linear, per-lane) ----
// layout [hi/lo][ntile][kstep][lane], element = uint2 (b0,b1)
__device__ uint2 g_bqkv[2 * 72 * 12 * 32];   // 442 KB
__device__ uint2 g_bproj[2 * 24 * 12 * 32];  // 147 KB

__device__ __forceinline__ uint32_t pack_bf16(float a, float b, int lo) {
    __nv_bfloat16 ah = __float2bfloat16(a), bh = __float2bfloat16(b);
    if (lo) {
        ah = __float2bfloat16(a - __bfloat162float(ah));
        bh = __float2bfloat16(b - __bfloat162float(bh));
    }
    return (uint32_t)*(unsigned short*)&ah | ((uint32_t)*(unsigned short*)&bh << 16);
}

__global__ void prep_frags(const float* __restrict__ qkv_w,
                           const float* __restrict__ proj_w)
{
    int idx = blockIdx.x * blockDim.x + threadIdx.x;
    const int NQ = 2 * 72 * 12 * 32;          // 55296
    const int NP = 2 * 24 * 12 * 32;          // 18432
    if (idx >= NQ + NP) return;
    const float* W;
    uint2* dst;
    int e, hl;
    if (idx < NQ) {
        hl = idx / (72 * 12 * 32);
        e  = idx % (72 * 12 * 32);
        W = qkv_w; dst = g_bqkv + idx;
    } else {
        int i2 = idx - NQ;
        hl = i2 / (24 * 12 * 32);
        e  = i2 % (24 * 12 * 32);
        W = proj_w; dst = g_bproj + i2;
    }
    int lane = e & 31;
    int ks   = (e >> 5) % 12;
    int nt   = (e >> 5) / 12;
    int j = nt * 8 + (lane >> 2);
    int k = ks * 16 + (lane & 3) * 2;
    const float* wr = W + (size_t)j * DIM;
    uint2 v;
    v.x = pack_bf16(wr[k],     wr[k + 1], hl);
    v.y = pack_bf16(wr[k + 8], wr[k + 9], hl);
    *dst = v;
}

// ---- one GEMM chunk: 4 m-tiles x NT n-tiles x 12 k-steps, 3-term bf16 split ----
template <int NT>
__device__ __forceinline__ void gemm_chunk(uint32_t aHi, uint32_t aLo,
                                           const uint2* __restrict__ bhi,
                                           const uint2* __restrict__ blo,
                                           float acc[NT][4][4])
{
    #pragma unroll
    for (int n = 0; n < NT; n++)
        #pragma unroll
        for (int m = 0; m < 4; m++)
            #pragma unroll
            for (int q = 0; q < 4; q++) acc[n][m][q] = 0.f;

    #pragma unroll
    for (int ks = 0; ks < 12; ks++) {
        uint2 bh[NT], bl[NT];
        #pragma unroll
        for (int n = 0; n < NT; n++) {
            bh[n] = bhi[(n * 12 + ks) * 32];
            bl[n] = blo[(n * 12 + ks) * 32];
        }
        uint32_t ah[4][4], al[4][4];
        #pragma unroll
        for (int m = 0; m < 4; m++) {
            ldm4(ah[m], aHi + m * 6400 + ks * 32);
            ldm4(al[m], aLo + m * 6400 + ks * 32);
        }
        #pragma unroll
        for (int n = 0; n < NT; n++)
            #pragma unroll
            for (int m = 0; m < 4; m++) {
                mma16816(acc[n][m], ah[m], bh[n]);
                mma16816(acc[n][m], al[m], bh[n]);
                mma16816(acc[n][m], ah[m], bl[n]);
            }
    }
}

extern "C" __global__ void __launch_bounds__(THREADS, 1)
win_attn_kernel(const float* __restrict__ x,
                const int* __restrict__ rpi_raw,
                const float* __restrict__ mask,
                const float* __restrict__ qkv_b,
                const float* __restrict__ proj_b,
                const float* __restrict__ rpb,
                float* __restrict__ out)
{
    extern __shared__ char smem[];
    __nv_bfloat16* xhi = (__nv_bfloat16*)(smem + SM_XHI);
    __nv_bfloat16* xlo = (__nv_bfloat16*)(smem + SM_XLO);
    float* qkvs  = (float*)(smem + SM_QKVS);
    float* masks = (float*)(smem + SM_MASK);
    float* rpbs  = (float*)(smem + SM_RPB);
    int*   rpis  = (int*)(smem + SM_RPI);

    const int tid  = threadIdx.x;
    const int bw   = blockIdx.x;
    const int widx = bw & 63;
    const int lane = tid & 31, warp = tid >> 5;
    const int gid = lane >> 2, tig = lane & 3;

    // ldmatrix per-lane base addresses into xs (hi/lo)
    const int rowA = (lane & 7) + ((lane >> 3) & 1) * 8;
    const int colA = (lane >> 4) * 8;
    const uint32_t aHi = smem_u32(smem) + SM_XHI + (uint32_t)(rowA * XS_STRIDE + colA) * 2;
    const uint32_t aLo = aHi + (SM_XLO - SM_XHI);

    // ---------------- Phase 1: stage ----------------
    {
        const float* xg = x + (size_t)bw * (NTOK * DIM);
        for (int i = tid; i < 64 * DIM; i += THREADS) {
            int r = i / DIM, k = i - r * DIM;
            float v = (r < NTOK) ? xg[i] : 0.f;
            __nv_bfloat16 h = __float2bfloat16(v);
            xhi[r * XS_STRIDE + k] = h;
            xlo[r * XS_STRIDE + k] = __float2bfloat16(v - __bfloat162float(h));
        }
        const float* mg = mask + (size_t)widx * (NTOK * NTOK);
        for (int i = tid; i < NTOK * NTOK; i += THREADS) masks[i] = mg[i];
        bool is64 = (rpi_raw[1] == 0) && (rpi_raw[3] == 0) && (rpi_raw[5] == 0)
                 && (rpi_raw[7] == 0) && (rpi_raw[9] == 0);
        for (int i = tid; i < NTOK * NTOK; i += THREADS)
            rpis[i] = is64 ? rpi_raw[2 * i] : rpi_raw[i];
        for (int i = tid; i < TABLE * HEADS; i += THREADS) rpbs[i] = rpb[i];
    }
    __syncthreads();

    // ---------------- Phase 2: QKV GEMM via mma.sync ----------------
    #pragma unroll 1
    for (int c = 0; c < 2; c++) {
        const int ntbase = warp * 6 + c * 3;
        const uint2* bhi = g_bqkv + (size_t)ntbase * 384 + lane;
        const uint2* blo = bhi + 72 * 12 * 32;
        float acc[3][4][4];
        gemm_chunk<3>(aHi, aLo, bhi, blo, acc);
        #pragma unroll
        for (int n = 0; n < 3; n++) {
            int col = (ntbase + n) * 8 + tig * 2;
            float b0 = qkv_b[col], b1 = qkv_b[col + 1];
            #pragma unroll
            for (int m = 0; m < 4; m++) {
                int r0 = m * 16 + gid;
                if (r0 < NTOK)
                    *(float2*)(qkvs + r0 * QS_STRIDE + col) =
                        make_float2(acc[n][m][0] + b0, acc[n][m][1] + b1);
                if (r0 + 8 < NTOK)
                    *(float2*)(qkvs + (r0 + 8) * QS_STRIDE + col) =
                        make_float2(acc[n][m][2] + b0, acc[n][m][3] + b1);
            }
        }
    }
    __syncthreads();

    // ---------------- Phase 3: warp-per-head register attention ----------------
    // output written as bf16 hi/lo directly into xs buffers (proj A input)
    {
        const float scale = 0.17677669529663687f;
        const int h    = warp >> 1;
        const int half = warp & 1;
        const int nrows = half ? 24 : 25;
        const bool act = lane < nrows;
        const int i = half * 25 + (act ? lane : 0);
        const int qo = h * 32, ko = DIM + h * 32, vo = 2 * DIM + h * 32;

        ull q2[16];
        {
            const ulonglong2* qv = (const ulonglong2*)(qkvs + i * QS_STRIDE + qo);
            #pragma unroll
            for (int p = 0; p < 8; p++) {
                ulonglong2 t = qv[p];
                q2[2 * p] = t.x; q2[2 * p + 1] = t.y;
            }
        }
        const int*   rp = rpis + i * NTOK;
        const float* mk = masks + i * NTOK;

        float srow[NTOK];
        #pragma unroll
        for (int j = 0; j < NTOK; j++) {
            const ulonglong2* kv = (const ulonglong2*)(qkvs + j * QS_STRIDE + ko);
            ull a0 = 0ull, a1 = 0ull;
            #pragma unroll
            for (int p = 0; p < 8; p++) {
                ulonglong2 k2 = kv[p];
                fma2(a0, q2[2 * p], k2.x);
                fma2(a1, q2[2 * p + 1], k2.y);
            }
            srow[j] = (unpack_sum(a0) + unpack_sum(a1)) * scale
                    + rpbs[rp[j] * HEADS + h] + mk[j];
        }
        float m = -1e30f;
        #pragma unroll
        for (int j = 0; j < NTOK; j++) m = fmaxf(m, srow[j]);
        float sum = 0.f;
        #pragma unroll
        for (int j = 0; j < NTOK; j++) {
            float ev = __expf(srow[j] - m);
            srow[j] = ev; sum += ev;
        }
        float inv = 1.f / sum;
        #pragma unroll
        for (int j = 0; j < NTOK; j++) srow[j] *= inv;

        ull acc[16];
        #pragma unroll
        for (int p = 0; p < 16; p++) acc[p] = 0ull;
        #pragma unroll
        for (int j = 0; j < NTOK; j++) {
            const ulonglong2* vv = (const ulonglong2*)(qkvs + j * QS_STRIDE + vo);
            ull aj = dup2(srow[j]);
            #pragma unroll
            for (int p = 0; p < 8; p++) {
                ulonglong2 v2 = vv[p];
                fma2(acc[2 * p], aj, v2.x);
                fma2(acc[2 * p + 1], aj, v2.y);
            }
        }
        if (act) {
            __nv_bfloat162* hr = (__nv_bfloat162*)(xhi + i * XS_STRIDE + qo);
            __nv_bfloat162* lr = (__nv_bfloat162*)(xlo + i * XS_STRIDE + qo);
            #pragma unroll
            for (int p = 0; p < 16; p++) {
                float f0, f1;
                unpack2(acc[p], f0, f1);
                __nv_bfloat16 h0 = __float2bfloat16(f0);
                __nv_bfloat16 h1 = __float2bfloat16(f1);
                __nv_bfloat16 l0 = __float2bfloat16(f0 - __bfloat162float(h0));
                __nv_bfloat16 l1 = __float2bfloat16(f1 - __bfloat162float(h1));
                hr[p] = __nv_bfloat162(h0, h1);
                lr[p] = __nv_bfloat162(l0, l1);
            }
        }
    }
    __syncthreads();

    // ---------------- Phase 4: proj GEMM via mma.sync ----------------
    {
        const int ntbase = warp * 2;
        const uint2* bhi = g_bproj + (size_t)ntbase * 384 + lane;
        const uint2* blo = bhi + 24 * 12 * 32;
        float acc[2][4][4];
        gemm_chunk<2>(aHi, aLo, bhi, blo, acc);
        float* og = out + (size_t)bw * (NTOK * DIM);
        #pragma unroll
        for (int n = 0; n < 2; n++) {
            int col = (ntbase + n) * 8 + tig * 2;
            float b0 = proj_b[col], b1 = proj_b[col + 1];
            #pragma unroll
            for (int m = 0; m < 4; m++) {
                int r0 = m * 16 + gid;
                if (r0 < NTOK)
                    *(float2*)(og + r0 * DIM + col) =
                        make_float2(acc[n][m][0] + b0, acc[n][m][1] + b1);
                if (r0 + 8 < NTOK)
                    *(float2*)(og + (r0 + 8) * DIM + col) =
                        make_float2(acc[n][m][2] + b0, acc[n][m][3] + b1);
            }
        }
    }
}

extern "C" void kernel_launch(void* const* d_in, const int* in_sizes, int n_in,
                              void* d_out, int out_size)
{
    const float* x      = (const float*)d_in[0];
    const int*   rpi    = (const int*)d_in[1];
    const float* mask   = (const float*)d_in[2];
    const float* qkv_w  = (const float*)d_in[3];
    const float* qkv_b  = (const float*)d_in[4];
    const float* proj_w = (const float*)d_in[5];
    const float* proj_b = (const float*)d_in[6];
    const float* rpb    = (const float*)d_in[7];

    prep_frags<<<(2 * 72 * 12 * 32 + 2 * 24 * 12 * 32 + 255) / 256, 256>>>(qkv_w, proj_w);

    cudaFuncSetAttribute(win_attn_kernel,
                         cudaFuncAttributeMaxDynamicSharedMemorySize, SM_TOTAL);
    win_attn_kernel<<<4096, THREADS, SM_TOTAL>>>(x, rpi, mask, qkv_b,
                                                 proj_b, rpb, (float*)d_out);
}

// round 8
// speedup vs baseline: 6.1886x; 1.1894x over previous
#include <cuda_runtime.h>
#include <cuda_bf16.h>
#include <cstdint>

#define HEADS 6
#define DIM 192
#define NTOK 49
#define THREADS 384
#define ST 200                 // bf16 row stride (400B)

// smem byte offsets
#define SM_XHI   0             // [64][200] bf16
#define SM_XLO   25600
#define SM_QHI   51200
#define SM_QLO   76800
#define SM_KHI   102400        // [56][200]
#define SM_KLO   124800
#define SM_VHI   147200        // [64][200]
#define SM_VLO   172800
#define SM_TOTAL 198400

// ---- helpers ----
__device__ __forceinline__ uint32_t smem_u32(const void* p) {
    uint32_t a;
    asm("{ .reg .u64 t; cvta.to.shared.u64 t, %1; cvt.u32.u64 %0, t; }" : "=r"(a) : "l"(p));
    return a;
}
__device__ __forceinline__ void ldm4(uint32_t* r, uint32_t addr) {
    asm volatile("ldmatrix.sync.aligned.m8n8.x4.shared.b16 {%0,%1,%2,%3}, [%4];"
        : "=r"(r[0]), "=r"(r[1]), "=r"(r[2]), "=r"(r[3]) : "r"(addr));
}
__device__ __forceinline__ void ldm2(uint32_t* r, uint32_t addr) {
    asm volatile("ldmatrix.sync.aligned.m8n8.x2.shared.b16 {%0,%1}, [%2];"
        : "=r"(r[0]), "=r"(r[1]) : "r"(addr));
}
__device__ __forceinline__ void ldm2t(uint32_t* r, uint32_t addr) {
    asm volatile("ldmatrix.sync.aligned.m8n8.x2.trans.shared.b16 {%0,%1}, [%2];"
        : "=r"(r[0]), "=r"(r[1]) : "r"(addr));
}
__device__ __forceinline__ void mma16816(float* c, const uint32_t* a, uint2 b) {
    asm volatile("mma.sync.aligned.m16n8k16.row.col.f32.bf16.bf16.f32 "
        "{%0,%1,%2,%3},{%4,%5,%6,%7},{%8,%9},{%0,%1,%2,%3};"
        : "+f"(c[0]), "+f"(c[1]), "+f"(c[2]), "+f"(c[3])
        : "r"(a[0]), "r"(a[1]), "r"(a[2]), "r"(a[3]), "r"(b.x), "r"(b.y));
}
__device__ __forceinline__ uint32_t hpack(float a, float b) {
    __nv_bfloat16 ah = __float2bfloat16(a), bh = __float2bfloat16(b);
    return (uint32_t)*(unsigned short*)&ah | ((uint32_t)*(unsigned short*)&bh << 16);
}
__device__ __forceinline__ uint32_t lpack(float a, float b) {
    float ha = __bfloat162float(__float2bfloat16(a));
    float hb = __bfloat162float(__float2bfloat16(b));
    return hpack(a - ha, b - hb);
}
__device__ __forceinline__ void st_hilo(__nv_bfloat16* dh, __nv_bfloat16* dl,
                                        int off, float a, float b) {
    *(uint32_t*)(dh + off) = hpack(a, b);
    *(uint32_t*)(dl + off) = lpack(a, b);
}

// ---- pre-packed weight B fragments ----
__device__ uint2 g_bqkv[2 * 72 * 12 * 32];
__device__ uint2 g_bproj[2 * 24 * 12 * 32];
// combined bias+mask, bf16x2 pairs: [64][6][49][28]
#define CM_N (64 * 6 * 49 * 28)
__device__ uint32_t g_cmask[CM_N];

__device__ __forceinline__ uint32_t pack_w(float a, float b, int lo) {
    return lo ? lpack(a, b) : hpack(a, b);
}

__global__ void prep_frags(const float* __restrict__ qkv_w,
                           const float* __restrict__ proj_w)
{
    int idx = blockIdx.x * blockDim.x + threadIdx.x;
    const int NQ = 2 * 72 * 12 * 32, NP = 2 * 24 * 12 * 32;
    if (idx >= NQ + NP) return;
    const float* W; uint2* dst; int e, hl;
    if (idx < NQ) { hl = idx / (72*12*32); e = idx % (72*12*32); W = qkv_w; dst = g_bqkv + idx; }
    else { int i2 = idx - NQ; hl = i2 / (24*12*32); e = i2 % (24*12*32); W = proj_w; dst = g_bproj + i2; }
    int lane = e & 31, ks = (e >> 5) % 12, nt = (e >> 5) / 12;
    int j = nt * 8 + (lane >> 2);
    int k = ks * 16 + (lane & 3) * 2;
    const float* wr = W + (size_t)j * DIM;
    uint2 v;
    v.x = pack_w(wr[k],     wr[k + 1], hl);
    v.y = pack_w(wr[k + 8], wr[k + 9], hl);
    *dst = v;
}

__global__ void prep_cmask(const int* __restrict__ rpi_raw,
                           const float* __restrict__ mask,
                           const float* __restrict__ rpb)
{
    int idx = blockIdx.x * blockDim.x + threadIdx.x;
    if (idx >= CM_N) return;
    int jp = idx % 28;
    int i  = (idx / 28) % 49;
    int h  = (idx / (28 * 49)) % 6;
    int w  = idx / (28 * 49 * 6);
    bool is64 = (rpi_raw[1] == 0) && (rpi_raw[3] == 0) && (rpi_raw[5] == 0)
             && (rpi_raw[7] == 0) && (rpi_raw[9] == 0);
    float v[2];
    #pragma unroll
    for (int t = 0; t < 2; t++) {
        int j = jp * 2 + t;
        if (j < 49) {
            int e = i * 49 + j;
            int r = is64 ? rpi_raw[2 * e] : rpi_raw[e];
            v[t] = rpb[r * 6 + h] + mask[w * 2401 + e];
        } else v[t] = -30000.f;
    }
    g_cmask[idx] = hpack(v[0], v[1]);
}

// ---- GEMM chunk (validated in R7): 4 m-tiles x NT n-tiles x 12 k-steps ----
template <int NT>
__device__ __forceinline__ void gemm_chunk(uint32_t aHi, uint32_t aLo,
                                           const uint2* __restrict__ bhi,
                                           const uint2* __restrict__ blo,
                                           float acc[NT][4][4])
{
    #pragma unroll
    for (int n = 0; n < NT; n++)
        #pragma unroll
        for (int m = 0; m < 4; m++)
            #pragma unroll
            for (int q = 0; q < 4; q++) acc[n][m][q] = 0.f;
    #pragma unroll
    for (int ks = 0; ks < 12; ks++) {
        uint2 bh[NT], bl[NT];
        #pragma unroll
        for (int n = 0; n < NT; n++) {
            bh[n] = bhi[(n * 12 + ks) * 32];
            bl[n] = blo[(n * 12 + ks) * 32];
        }
        uint32_t ah[4][4], al[4][4];
        #pragma unroll
        for (int m = 0; m < 4; m++) {
            ldm4(ah[m], aHi + m * 6400 + ks * 32);
            ldm4(al[m], aLo + m * 6400 + ks * 32);
        }
        #pragma unroll
        for (int n = 0; n < NT; n++)
            #pragma unroll
            for (int m = 0; m < 4; m++) {
                mma16816(acc[n][m], ah[m], bh[n]);
                mma16816(acc[n][m], al[m], bh[n]);
                mma16816(acc[n][m], ah[m], bl[n]);
            }
    }
}

extern "C" __global__ void __launch_bounds__(THREADS, 1)
win_attn_kernel(const float* __restrict__ x,
                const float* __restrict__ qkv_b,
                const float* __restrict__ proj_b,
                float* __restrict__ out)
{
    extern __shared__ char smem[];
    __nv_bfloat16* xhi = (__nv_bfloat16*)(smem + SM_XHI);
    __nv_bfloat16* xlo = (__nv_bfloat16*)(smem + SM_XLO);
    __nv_bfloat16* qhi = (__nv_bfloat16*)(smem + SM_QHI);
    __nv_bfloat16* qlo = (__nv_bfloat16*)(smem + SM_QLO);
    __nv_bfloat16* khi = (__nv_bfloat16*)(smem + SM_KHI);
    __nv_bfloat16* klo = (__nv_bfloat16*)(smem + SM_KLO);
    __nv_bfloat16* vhi = (__nv_bfloat16*)(smem + SM_VHI);
    __nv_bfloat16* vlo = (__nv_bfloat16*)(smem + SM_VLO);

    const int tid  = threadIdx.x;
    const int bw   = blockIdx.x;
    const int widx = bw & 63;
    const int lane = tid & 31, warp = tid >> 5;
    const int gid = lane >> 2, tig = lane & 3;
    const uint32_t sb = smem_u32(smem);

    // ldmatrix A-operand lane addressing (validated in R7)
    const int rowA = (lane & 7) + ((lane >> 3) & 1) * 8;
    const int colA = (lane >> 4) * 8;
    const uint32_t aHi = sb + SM_XHI + (uint32_t)(rowA * ST + colA) * 2;
    const uint32_t aLo = aHi + (SM_XLO - SM_XHI);

    // ---------------- Phase 1: stage x -> bf16 hi/lo; zero pad rows ----------------
    {
        const float* xg = x + (size_t)bw * (NTOK * DIM);
        for (int i = tid; i < 64 * DIM; i += THREADS) {
            int r = i / DIM, k = i - r * DIM;
            float v = (r < NTOK) ? xg[i] : 0.f;
            __nv_bfloat16 h = __float2bfloat16(v);
            xhi[r * ST + k] = h;
            xlo[r * ST + k] = __float2bfloat16(v - __bfloat162float(h));
        }
        // zero rows 49..63 of q/v (and 49..55 of k), as u32
        uint32_t* q32h = (uint32_t*)qhi; uint32_t* q32l = (uint32_t*)qlo;
        uint32_t* k32h = (uint32_t*)khi; uint32_t* k32l = (uint32_t*)klo;
        uint32_t* v32h = (uint32_t*)vhi; uint32_t* v32l = (uint32_t*)vlo;
        for (int i = tid; i < 15 * 100; i += THREADS) {
            int r = 49 + i / 100, c = i % 100;
            int o = r * 100 + c;
            q32h[o] = 0; q32l[o] = 0; v32h[o] = 0; v32l[o] = 0;
            if (r < 56) { k32h[o] = 0; k32l[o] = 0; }
        }
    }
    __syncthreads();

    // ---------------- Phase 2: QKV GEMM -> Q/K/V bf16 hi/lo ----------------
    {
        const int g = warp >> 2;   // 0=Q 1=K 2=V (48 cols per warp, within one matrix)
        __nv_bfloat16* dh = (g == 0) ? qhi : (g == 1) ? khi : vhi;
        __nv_bfloat16* dl = (g == 0) ? qlo : (g == 1) ? klo : vlo;
        #pragma unroll 1
        for (int c = 0; c < 2; c++) {
            const int ntbase = warp * 6 + c * 3;
            const uint2* bhi = g_bqkv + (size_t)ntbase * 384 + lane;
            const uint2* blo = bhi + 72 * 12 * 32;
            float acc[3][4][4];
            gemm_chunk<3>(aHi, aLo, bhi, blo, acc);
            #pragma unroll
            for (int n = 0; n < 3; n++) {
                int col = (ntbase + n) * 8 + tig * 2;
                int cc = col - g * 192;
                float b0 = qkv_b[col], b1 = qkv_b[col + 1];
                #pragma unroll
                for (int m = 0; m < 4; m++) {
                    int r0 = m * 16 + gid;
                    if (r0 < NTOK)
                        st_hilo(dh, dl, r0 * ST + cc, acc[n][m][0] + b0, acc[n][m][1] + b1);
                    if (r0 + 8 < NTOK)
                        st_hilo(dh, dl, (r0 + 8) * ST + cc, acc[n][m][2] + b0, acc[n][m][3] + b1);
                }
            }
        }
    }
    __syncthreads();

    // ---------------- Phase 3: attention via mma (warp = head x row-half) ----------------
    {
        const float scale = 0.17677669529663687f;  // 32^-0.5
        const int h  = warp >> 1;
        const int mh = warp & 1;
        const int qo = h * 32;
        const uint32_t* cm = g_cmask + ((size_t)(widx * 6 + h) * 49) * 28;

        // Q a-frag base (head cols), K b-frag base, V b-frag base (trans)
        const uint32_t aQh = sb + SM_QHI + (uint32_t)((mh * 32 + rowA) * ST + qo + colA) * 2;
        const uint32_t aQl = aQh + (SM_QLO - SM_QHI);
        const int kr = lane & 7, km = (lane >> 3) & 1;
        const uint32_t bKh = sb + SM_KHI + (uint32_t)(kr * ST + qo + km * 8) * 2;
        const uint32_t bKl = bKh + (SM_KLO - SM_KHI);
        const uint32_t bVh = sb + SM_VHI + (uint32_t)((kr + km * 8) * ST + qo) * 2;
        const uint32_t bVl = bVh + (SM_VLO - SM_VHI);

        #pragma unroll 1
        for (int m = 0; m < 2; m++) {
            const int i0 = mh * 32 + m * 16 + gid;
            const int i1 = i0 + 8;

            // ---- scores: S = Q K^T (3-term) ----
            float sc[7][4];
            #pragma unroll
            for (int n = 0; n < 7; n++)
                #pragma unroll
                for (int q = 0; q < 4; q++) sc[n][q] = 0.f;
            #pragma unroll
            for (int ks = 0; ks < 2; ks++) {
                uint32_t ah[4], al[4];
                ldm4(ah, aQh + m * 6400 + ks * 32);
                ldm4(al, aQl + m * 6400 + ks * 32);
                #pragma unroll
                for (int n = 0; n < 7; n++) {
                    uint32_t bh[2], bl[2];
                    ldm2(bh, bKh + n * 3200 + ks * 32);
                    ldm2(bl, bKl + n * 3200 + ks * 32);
                    uint2 BH = make_uint2(bh[0], bh[1]);
                    uint2 BL = make_uint2(bl[0], bl[1]);
                    mma16816(sc[n], ah, BH);
                    mma16816(sc[n], al, BH);
                    mma16816(sc[n], ah, BL);
                }
            }

            // ---- scale + bias+mask ----
            #pragma unroll
            for (int n = 0; n < 7; n++) {
                if (i0 < NTOK) {
                    uint32_t cp = cm[i0 * 28 + n * 4 + tig];
                    __nv_bfloat162 cf = *(__nv_bfloat162*)&cp;
                    sc[n][0] = sc[n][0] * scale + __bfloat162float(cf.x);
                    sc[n][1] = sc[n][1] * scale + __bfloat162float(cf.y);
                } else { sc[n][0] = -30000.f; sc[n][1] = -30000.f; }
                if (i1 < NTOK) {
                    uint32_t cp = cm[i1 * 28 + n * 4 + tig];
                    __nv_bfloat162 cf = *(__nv_bfloat162*)&cp;
                    sc[n][2] = sc[n][2] * scale + __bfloat162float(cf.x);
                    sc[n][3] = sc[n][3] * scale + __bfloat162float(cf.y);
                } else { sc[n][2] = -30000.f; sc[n][3] = -30000.f; }
            }

            // ---- row softmax (rows i0, i1; reduce across tig via shfl) ----
            float mA = -1e30f, mB = -1e30f;
            #pragma unroll
            for (int n = 0; n < 7; n++) {
                mA = fmaxf(mA, fmaxf(sc[n][0], sc[n][1]));
                mB = fmaxf(mB, fmaxf(sc[n][2], sc[n][3]));
            }
            mA = fmaxf(mA, __shfl_xor_sync(0xffffffffu, mA, 1));
            mA = fmaxf(mA, __shfl_xor_sync(0xffffffffu, mA, 2));
            mB = fmaxf(mB, __shfl_xor_sync(0xffffffffu, mB, 1));
            mB = fmaxf(mB, __shfl_xor_sync(0xffffffffu, mB, 2));
            float sA = 0.f, sB = 0.f;
            #pragma unroll
            for (int n = 0; n < 7; n++) {
                sc[n][0] = __expf(sc[n][0] - mA); sA += sc[n][0];
                sc[n][1] = __expf(sc[n][1] - mA); sA += sc[n][1];
                sc[n][2] = __expf(sc[n][2] - mB); sB += sc[n][2];
                sc[n][3] = __expf(sc[n][3] - mB); sB += sc[n][3];
            }
            sA += __shfl_xor_sync(0xffffffffu, sA, 1);
            sA += __shfl_xor_sync(0xffffffffu, sA, 2);
            sB += __shfl_xor_sync(0xffffffffu, sB, 1);
            sB += __shfl_xor_sync(0xffffffffu, sB, 2);
            float rA = 1.f / sA, rB = 1.f / sB;
            #pragma unroll
            for (int n = 0; n < 7; n++) {
                sc[n][0] *= rA; sc[n][1] *= rA;
                sc[n][2] *= rB; sc[n][3] *= rB;
            }

            // ---- repack P fragments (hi/lo) straight from accumulators ----
            uint32_t ph[4][4], pl[4][4];
            #pragma unroll
            for (int jt = 0; jt < 4; jt++) {
                int nA = 2 * jt, nB = 2 * jt + 1;
                ph[jt][0] = hpack(sc[nA][0], sc[nA][1]);
                pl[jt][0] = lpack(sc[nA][0], sc[nA][1]);
                ph[jt][1] = hpack(sc[nA][2], sc[nA][3]);
                pl[jt][1] = lpack(sc[nA][2], sc[nA][3]);
                if (nB < 7) {
                    ph[jt][2] = hpack(sc[nB][0], sc[nB][1]);
                    pl[jt][2] = lpack(sc[nB][0], sc[nB][1]);
                    ph[jt][3] = hpack(sc[nB][2], sc[nB][3]);
                    pl[jt][3] = lpack(sc[nB][2], sc[nB][3]);
                } else {
                    ph[jt][2] = 0; pl[jt][2] = 0; ph[jt][3] = 0; pl[jt][3] = 0;
                }
            }

            // ---- AV: out = P V (3-term), V via ldmatrix.trans ----
            float av[4][4];
            #pragma unroll
            for (int nd = 0; nd < 4; nd++)
                #pragma unroll
                for (int q = 0; q < 4; q++) av[nd][q] = 0.f;
            #pragma unroll
            for (int jt = 0; jt < 4; jt++) {
                #pragma unroll
                for (int nd = 0; nd < 4; nd++) {
                    uint32_t bh[2], bl[2];
                    ldm2t(bh, bVh + jt * 16 * 400 + nd * 16);
                    ldm2t(bl, bVl + jt * 16 * 400 + nd * 16);
                    uint2 BH = make_uint2(bh[0], bh[1]);
                    uint2 BL = make_uint2(bl[0], bl[1]);
                    mma16816(av[nd], ph[jt], BH);
                    mma16816(av[nd], pl[jt], BH);
                    mma16816(av[nd], ph[jt], BL);
                }
            }

            // ---- store AV out as proj A input (bf16 hi/lo into x buffers) ----
            #pragma unroll
            for (int nd = 0; nd < 4; nd++) {
                int col = qo + nd * 8 + tig * 2;
                if (i0 < NTOK) st_hilo(xhi, xlo, i0 * ST + col, av[nd][0], av[nd][1]);
                if (i1 < NTOK) st_hilo(xhi, xlo, i1 * ST + col, av[nd][2], av[nd][3]);
            }
        }
    }
    __syncthreads();

    // ---------------- Phase 4: proj GEMM (unchanged from R7) ----------------
    {
        const int ntbase = warp * 2;
        const uint2* bhi = g_bproj + (size_t)ntbase * 384 + lane;
        const uint2* blo = bhi + 24 * 12 * 32;
        float acc[2][4][4];
        gemm_chunk<2>(aHi, aLo, bhi, blo, acc);
        float* og = out + (size_t)bw * (NTOK * DIM);
        #pragma unroll
        for (int n = 0; n < 2; n++) {
            int col = (ntbase + n) * 8 + tig * 2;
            float b0 = proj_b[col], b1 = proj_b[col + 1];
            #pragma unroll
            for (int m = 0; m < 4; m++) {
                int r0 = m * 16 + gid;
                if (r0 < NTOK)
                    *(float2*)(og + r0 * DIM + col) =
                        make_float2(acc[n][m][0] + b0, acc[n][m][1] + b1);
                if (r0 + 8 < NTOK)
                    *(float2*)(og + (r0 + 8) * DIM + col) =
                        make_float2(acc[n][m][2] + b0, acc[n][m][3] + b1);
            }
        }
    }
}

extern "C" void kernel_launch(void* const* d_in, const int* in_sizes, int n_in,
                              void* d_out, int out_size)
{
    const float* x      = (const float*)d_in[0];
    const int*   rpi    = (const int*)d_in[1];
    const float* mask   = (const float*)d_in[2];
    const float* qkv_w  = (const float*)d_in[3];
    const float* qkv_b  = (const float*)d_in[4];
    const float* proj_w = (const float*)d_in[5];
    const float* proj_b = (const float*)d_in[6];
    const float* rpb    = (const float*)d_in[7];

    prep_frags<<<(2 * 72 * 12 * 32 + 2 * 24 * 12 * 32 + 255) / 256, 256>>>(qkv_w, proj_w);
    prep_cmask<<<(CM_N + 255) / 256, 256>>>(rpi, mask, rpb);

    cudaFuncSetAttribute(win_attn_kernel,
                         cudaFuncAttributeMaxDynamicSharedMemorySize, SM_TOTAL);
    win_attn_kernel<<<4096, THREADS, SM_TOTAL>>>(x, qkv_b, proj_b, (float*)d_out);
}

// round 9
// speedup vs baseline: 8.0579x; 1.3021x over previous
#include <cuda_runtime.h>
#include <cuda_fp16.h>
#include <cstdint>

#define HEADS 6
#define DIM 192
#define NTOK 49
#define THREADS 384
#define ST 200                 // fp16 row stride (400B)

// smem byte offsets
#define SM_XHI   0             // [64][200] fp16
#define SM_XLO   25600
#define SM_QHI   51200
#define SM_QLO   76800
#define SM_KHI   102400        // [56][200]
#define SM_VHI   124800        // [64][200]
#define SM_TOTAL 150400

// ---- helpers ----
__device__ __forceinline__ uint32_t smem_u32(const void* p) {
    uint32_t a;
    asm("{ .reg .u64 t; cvta.to.shared.u64 t, %1; cvt.u32.u64 %0, t; }" : "=r"(a) : "l"(p));
    return a;
}
__device__ __forceinline__ void ldm4(uint32_t* r, uint32_t addr) {
    asm volatile("ldmatrix.sync.aligned.m8n8.x4.shared.b16 {%0,%1,%2,%3}, [%4];"
        : "=r"(r[0]), "=r"(r[1]), "=r"(r[2]), "=r"(r[3]) : "r"(addr));
}
__device__ __forceinline__ void ldm2(uint32_t* r, uint32_t addr) {
    asm volatile("ldmatrix.sync.aligned.m8n8.x2.shared.b16 {%0,%1}, [%2];"
        : "=r"(r[0]), "=r"(r[1]) : "r"(addr));
}
__device__ __forceinline__ void ldm2t(uint32_t* r, uint32_t addr) {
    asm volatile("ldmatrix.sync.aligned.m8n8.x2.trans.shared.b16 {%0,%1}, [%2];"
        : "=r"(r[0]), "=r"(r[1]) : "r"(addr));
}
__device__ __forceinline__ void mma16816(float* c, const uint32_t* a, uint2 b) {
    asm volatile("mma.sync.aligned.m16n8k16.row.col.f32.f16.f16.f32 "
        "{%0,%1,%2,%3},{%4,%5,%6,%7},{%8,%9},{%0,%1,%2,%3};"
        : "+f"(c[0]), "+f"(c[1]), "+f"(c[2]), "+f"(c[3])
        : "r"(a[0]), "r"(a[1]), "r"(a[2]), "r"(a[3]), "r"(b.x), "r"(b.y));
}
__device__ __forceinline__ uint32_t hpack(float a, float b) {
    __half2 h = __floats2half2_rn(a, b);
    return *(uint32_t*)&h;
}
__device__ __forceinline__ uint32_t lpack(float a, float b) {
    float ha = __half2float(__float2half_rn(a));
    float hb = __half2float(__float2half_rn(b));
    return hpack(a - ha, b - hb);
}
__device__ __forceinline__ void st_hilo(__half* dh, __half* dl,
                                        int off, float a, float b) {
    *(uint32_t*)(dh + off) = hpack(a, b);
    *(uint32_t*)(dl + off) = lpack(a, b);
}

// ---- pre-packed weight B fragments (fp16 hi only, 2-term split) ----
#define NQF (72 * 12 * 32)
#define NPF (24 * 12 * 32)
__device__ uint2 g_bqkv[NQF];
__device__ uint2 g_bproj[NPF];
// combined bias+mask, fp16x2 pairs: [64][6][49][28]
#define CM_N (64 * 6 * 49 * 28)
__device__ uint32_t g_cmask[CM_N];

__global__ void prep_frags(const float* __restrict__ qkv_w,
                           const float* __restrict__ proj_w)
{
    int idx = blockIdx.x * blockDim.x + threadIdx.x;
    if (idx >= NQF + NPF) return;
    const float* W; uint2* dst; int e;
    if (idx < NQF) { e = idx; W = qkv_w; dst = g_bqkv + idx; }
    else { e = idx - NQF; W = proj_w; dst = g_bproj + e; }
    int lane = e & 31, ks = (e >> 5) % 12, nt = (e >> 5) / 12;
    int j = nt * 8 + (lane >> 2);
    int k = ks * 16 + (lane & 3) * 2;
    const float* wr = W + (size_t)j * DIM;
    uint2 v;
    v.x = hpack(wr[k],     wr[k + 1]);
    v.y = hpack(wr[k + 8], wr[k + 9]);
    *dst = v;
}

__global__ void prep_cmask(const int* __restrict__ rpi_raw,
                           const float* __restrict__ mask,
                           const float* __restrict__ rpb)
{
    int idx = blockIdx.x * blockDim.x + threadIdx.x;
    if (idx >= CM_N) return;
    int jp = idx % 28;
    int i  = (idx / 28) % 49;
    int h  = (idx / (28 * 49)) % 6;
    int w  = idx / (28 * 49 * 6);
    bool is64 = (rpi_raw[1] == 0) && (rpi_raw[3] == 0) && (rpi_raw[5] == 0)
             && (rpi_raw[7] == 0) && (rpi_raw[9] == 0);
    float v[2];
    #pragma unroll
    for (int t = 0; t < 2; t++) {
        int j = jp * 2 + t;
        if (j < 49) {
            int e = i * 49 + j;
            int r = is64 ? rpi_raw[2 * e] : rpi_raw[e];
            v[t] = rpb[r * 6 + h] + mask[w * 2401 + e];
        } else v[t] = -30000.f;
    }
    g_cmask[idx] = hpack(v[0], v[1]);
}

// ---- GEMM chunk: 4 m-tiles x NT n-tiles x 12 k-steps, 2-term fp16 split ----
template <int NT>
__device__ __forceinline__ void gemm_chunk(uint32_t aHi, uint32_t aLo,
                                           const uint2* __restrict__ bhi,
                                           float acc[NT][4][4])
{
    #pragma unroll
    for (int n = 0; n < NT; n++)
        #pragma unroll
        for (int m = 0; m < 4; m++)
            #pragma unroll
            for (int q = 0; q < 4; q++) acc[n][m][q] = 0.f;
    #pragma unroll
    for (int ks = 0; ks < 12; ks++) {
        uint2 bh[NT];
        #pragma unroll
        for (int n = 0; n < NT; n++) bh[n] = bhi[(n * 12 + ks) * 32];
        uint32_t ah[4][4], al[4][4];
        #pragma unroll
        for (int m = 0; m < 4; m++) {
            ldm4(ah[m], aHi + m * 6400 + ks * 32);
            ldm4(al[m], aLo + m * 6400 + ks * 32);
        }
        #pragma unroll
        for (int n = 0; n < NT; n++)
            #pragma unroll
            for (int m = 0; m < 4; m++) {
                mma16816(acc[n][m], ah[m], bh[n]);
                mma16816(acc[n][m], al[m], bh[n]);
            }
    }
}

extern "C" __global__ void __launch_bounds__(THREADS, 1)
win_attn_kernel(const float* __restrict__ x,
                const float* __restrict__ qkv_b,
                const float* __restrict__ proj_b,
                float* __restrict__ out)
{
    extern __shared__ char smem[];
    __half* xhi = (__half*)(smem + SM_XHI);
    __half* xlo = (__half*)(smem + SM_XLO);
    __half* qhi = (__half*)(smem + SM_QHI);
    __half* qlo = (__half*)(smem + SM_QLO);
    __half* khi = (__half*)(smem + SM_KHI);
    __half* vhi = (__half*)(smem + SM_VHI);

    const int tid  = threadIdx.x;
    const int bw   = blockIdx.x;
    const int widx = bw & 63;
    const int lane = tid & 31, warp = tid >> 5;
    const int gid = lane >> 2, tig = lane & 3;
    const uint32_t sb = smem_u32(smem);

    // ldmatrix A-operand lane addressing (validated R7/R8)
    const int rowA = (lane & 7) + ((lane >> 3) & 1) * 8;
    const int colA = (lane >> 4) * 8;
    const uint32_t aHi = sb + SM_XHI + (uint32_t)(rowA * ST + colA) * 2;
    const uint32_t aLo = aHi + (SM_XLO - SM_XHI);

    // ---------------- Phase 1: stage x -> fp16 hi/lo; zero pad rows ----------------
    {
        const float* xg = x + (size_t)bw * (NTOK * DIM);
        for (int i = tid; i < 64 * DIM; i += THREADS) {
            int r = i / DIM, k = i - r * DIM;
            float v = (r < NTOK) ? xg[i] : 0.f;
            __half h = __float2half_rn(v);
            xhi[r * ST + k] = h;
            xlo[r * ST + k] = __float2half_rn(v - __half2float(h));
        }
        uint32_t* q32h = (uint32_t*)qhi; uint32_t* q32l = (uint32_t*)qlo;
        uint32_t* k32h = (uint32_t*)khi; uint32_t* v32h = (uint32_t*)vhi;
        for (int i = tid; i < 15 * 100; i += THREADS) {
            int r = 49 + i / 100, c = i % 100;
            int o = r * 100 + c;
            q32h[o] = 0; q32l[o] = 0; v32h[o] = 0;
            if (r < 56) k32h[o] = 0;
        }
    }
    __syncthreads();

    // ---------------- Phase 2: QKV GEMM -> Q (hi/lo), K (hi), V (hi) ----------------
    {
        const int g = warp >> 2;   // 0=Q 1=K 2=V
        __half* dh = (g == 0) ? qhi : (g == 1) ? khi : vhi;
        #pragma unroll 1
        for (int c = 0; c < 2; c++) {
            const int ntbase = warp * 6 + c * 3;
            const uint2* bhi = g_bqkv + (size_t)ntbase * 384 + lane;
            float acc[3][4][4];
            gemm_chunk<3>(aHi, aLo, bhi, acc);
            #pragma unroll
            for (int n = 0; n < 3; n++) {
                int col = (ntbase + n) * 8 + tig * 2;
                int cc = col - g * 192;
                float b0 = qkv_b[col], b1 = qkv_b[col + 1];
                #pragma unroll
                for (int m = 0; m < 4; m++) {
                    int r0 = m * 16 + gid;
                    if (r0 < NTOK) {
                        if (g == 0) st_hilo(qhi, qlo, r0 * ST + cc,
                                            acc[n][m][0] + b0, acc[n][m][1] + b1);
                        else *(uint32_t*)(dh + r0 * ST + cc) =
                                 hpack(acc[n][m][0] + b0, acc[n][m][1] + b1);
                    }
                    if (r0 + 8 < NTOK) {
                        if (g == 0) st_hilo(qhi, qlo, (r0 + 8) * ST + cc,
                                            acc[n][m][2] + b0, acc[n][m][3] + b1);
                        else *(uint32_t*)(dh + (r0 + 8) * ST + cc) =
                                 hpack(acc[n][m][2] + b0, acc[n][m][3] + b1);
                    }
                }
            }
        }
    }
    __syncthreads();

    // ---------------- Phase 3: attention via mma (warp = head x row-half) ----------------
    {
        const float scale = 0.17677669529663687f;  // 32^-0.5
        const int h  = warp >> 1;
        const int mh = warp & 1;
        const int qo = h * 32;
        const uint32_t* cm = g_cmask + ((size_t)(widx * 6 + h) * 49) * 28;

        const uint32_t aQh = sb + SM_QHI + (uint32_t)((mh * 32 + rowA) * ST + qo + colA) * 2;
        const uint32_t aQl = aQh + (SM_QLO - SM_QHI);
        const int kr = lane & 7, km = (lane >> 3) & 1;
        const uint32_t bKh = sb + SM_KHI + (uint32_t)(kr * ST + qo + km * 8) * 2;
        const uint32_t bVh = sb + SM_VHI + (uint32_t)((kr + km * 8) * ST + qo) * 2;

        #pragma unroll 1
        for (int m = 0; m < 2; m++) {
            const int i0 = mh * 32 + m * 16 + gid;
            const int i1 = i0 + 8;

            // ---- scores: S = Q K^T (2-term) ----
            float sc[7][4];
            #pragma unroll
            for (int n = 0; n < 7; n++)
                #pragma unroll
                for (int q = 0; q < 4; q++) sc[n][q] = 0.f;
            #pragma unroll
            for (int ks = 0; ks < 2; ks++) {
                uint32_t ah[4], al[4];
                ldm4(ah, aQh + m * 6400 + ks * 32);
                ldm4(al, aQl + m * 6400 + ks * 32);
                #pragma unroll
                for (int n = 0; n < 7; n++) {
                    uint32_t bh[2];
                    ldm2(bh, bKh + n * 3200 + ks * 32);
                    uint2 BH = make_uint2(bh[0], bh[1]);
                    mma16816(sc[n], ah, BH);
                    mma16816(sc[n], al, BH);
                }
            }

            // ---- scale + bias+mask ----
            #pragma unroll
            for (int n = 0; n < 7; n++) {
                if (i0 < NTOK) {
                    uint32_t cp = cm[i0 * 28 + n * 4 + tig];
                    __half2 cf = *(__half2*)&cp;
                    sc[n][0] = sc[n][0] * scale + __half2float(cf.x);
                    sc[n][1] = sc[n][1] * scale + __half2float(cf.y);
                } else { sc[n][0] = -30000.f; sc[n][1] = -30000.f; }
                if (i1 < NTOK) {
                    uint32_t cp = cm[i1 * 28 + n * 4 + tig];
                    __half2 cf = *(__half2*)&cp;
                    sc[n][2] = sc[n][2] * scale + __half2float(cf.x);
                    sc[n][3] = sc[n][3] * scale + __half2float(cf.y);
                } else { sc[n][2] = -30000.f; sc[n][3] = -30000.f; }
            }

            // ---- row softmax (rows i0, i1; reduce across tig via shfl) ----
            float mA = -1e30f, mB = -1e30f;
            #pragma unroll
            for (int n = 0; n < 7; n++) {
                mA = fmaxf(mA, fmaxf(sc[n][0], sc[n][1]));
                mB = fmaxf(mB, fmaxf(sc[n][2], sc[n][3]));
            }
            mA = fmaxf(mA, __shfl_xor_sync(0xffffffffu, mA, 1));
            mA = fmaxf(mA, __shfl_xor_sync(0xffffffffu, mA, 2));
            mB = fmaxf(mB, __shfl_xor_sync(0xffffffffu, mB, 1));
            mB = fmaxf(mB, __shfl_xor_sync(0xffffffffu, mB, 2));
            float sA = 0.f, sB = 0.f;
            #pragma unroll
            for (int n = 0; n < 7; n++) {
                sc[n][0] = __expf(sc[n][0] - mA); sA += sc[n][0];
                sc[n][1] = __expf(sc[n][1] - mA); sA += sc[n][1];
                sc[n][2] = __expf(sc[n][2] - mB); sB += sc[n][2];
                sc[n][3] = __expf(sc[n][3] - mB); sB += sc[n][3];
            }
            sA += __shfl_xor_sync(0xffffffffu, sA, 1);
            sA += __shfl_xor_sync(0xffffffffu, sA, 2);
            sB += __shfl_xor_sync(0xffffffffu, sB, 1);
            sB += __shfl_xor_sync(0xffffffffu, sB, 2);
            float rA = 1.f / sA, rB = 1.f / sB;
            #pragma unroll
            for (int n = 0; n < 7; n++) {
                sc[n][0] *= rA; sc[n][1] *= rA;
                sc[n][2] *= rB; sc[n][3] *= rB;
            }

            // ---- repack P fragments (hi/lo fp16) straight from accumulators ----
            uint32_t ph[4][4], pl[4][4];
            #pragma unroll
            for (int jt = 0; jt < 4; jt++) {
                int nA = 2 * jt, nB = 2 * jt + 1;
                ph[jt][0] = hpack(sc[nA][0], sc[nA][1]);
                pl[jt][0] = lpack(sc[nA][0], sc[nA][1]);
                ph[jt][1] = hpack(sc[nA][2], sc[nA][3]);
                pl[jt][1] = lpack(sc[nA][2], sc[nA][3]);
                if (nB < 7) {
                    ph[jt][2] = hpack(sc[nB][0], sc[nB][1]);
                    pl[jt][2] = lpack(sc[nB][0], sc[nB][1]);
                    ph[jt][3] = hpack(sc[nB][2], sc[nB][3]);
                    pl[jt][3] = lpack(sc[nB][2], sc[nB][3]);
                } else {
                    ph[jt][2] = 0; pl[jt][2] = 0; ph[jt][3] = 0; pl[jt][3] = 0;
                }
            }

            // ---- AV: out = P V (2-term), V via ldmatrix.trans ----
            float av[4][4];
            #pragma unroll
            for (int nd = 0; nd < 4; nd++)
                #pragma unroll
                for (int q = 0; q < 4; q++) av[nd][q] = 0.f;
            #pragma unroll
            for (int jt = 0; jt < 4; jt++) {
                #pragma unroll
                for (int nd = 0; nd < 4; nd++) {
                    uint32_t bh[2];
                    ldm2t(bh, bVh + jt * 16 * 400 + nd * 16);
                    uint2 BH = make_uint2(bh[0], bh[1]);
                    mma16816(av[nd], ph[jt], BH);
                    mma16816(av[nd], pl[jt], BH);
                }
            }

            // ---- store AV out as proj A input (fp16 hi/lo into x buffers) ----
            #pragma unroll
            for (int nd = 0; nd < 4; nd++) {
                int col = qo + nd * 8 + tig * 2;
                if (i0 < NTOK) st_hilo(xhi, xlo, i0 * ST + col, av[nd][0], av[nd][1]);
                if (i1 < NTOK) st_hilo(xhi, xlo, i1 * ST + col, av[nd][2], av[nd][3]);
            }
        }
    }
    __syncthreads();

    // ---------------- Phase 4: proj GEMM (2-term) ----------------
    {
        const int ntbase = warp * 2;
        const uint2* bhi = g_bproj + (size_t)ntbase * 384 + lane;
        float acc[2][4][4];
        gemm_chunk<2>(aHi, aLo, bhi, acc);
        float* og = out + (size_t)bw * (NTOK * DIM);
        #pragma unroll
        for (int n = 0; n < 2; n++) {
            int col = (ntbase + n) * 8 + tig * 2;
            float b0 = proj_b[col], b1 = proj_b[col + 1];
            #pragma unroll
            for (int m = 0; m < 4; m++) {
                int r0 = m * 16 + gid;
                if (r0 < NTOK)
                    *(float2*)(og + r0 * DIM + col) =
                        make_float2(acc[n][m][0] + b0, acc[n][m][1] + b1);
                if (r0 + 8 < NTOK)
                    *(float2*)(og + (r0 + 8) * DIM + col) =
                        make_float2(acc[n][m][2] + b0, acc[n][m][3] + b1);
            }
        }
    }
}

extern "C" void kernel_launch(void* const* d_in, const int* in_sizes, int n_in,
                              void* d_out, int out_size)
{
    const float* x      = (const float*)d_in[0];
    const int*   rpi    = (const int*)d_in[1];
    const float* mask   = (const float*)d_in[2];
    const float* qkv_w  = (const float*)d_in[3];
    const float* qkv_b  = (const float*)d_in[4];
    const float* proj_w = (const float*)d_in[5];
    const float* proj_b = (const float*)d_in[6];
    const float* rpb    = (const float*)d_in[7];

    prep_frags<<<(NQF + NPF + 255) / 256, 256>>>(qkv_w, proj_w);
    prep_cmask<<<(CM_N + 255) / 256, 256>>>(rpi, mask, rpb);

    cudaFuncSetAttribute(win_attn_kernel,
                         cudaFuncAttributeMaxDynamicSharedMemorySize, SM_TOTAL);
    win_attn_kernel<<<4096, THREADS, SM_TOTAL>>>(x, qkv_b, proj_b, (float*)d_out);
}

// round 10
// speedup vs baseline: 9.9078x; 1.2296x over previous
#include <cuda_runtime.h>
#include <cuda_fp16.h>
#include <cstdint>

#define HEADS 6
#define DIM 192
#define NTOK 49
#define THREADS 384
#define ST 200                 // fp16 row stride (400B)

// smem byte offsets
#define SM_XHI   0             // [64][200] fp16
#define SM_XLO   25600
#define SM_QHI   51200
#define SM_QLO   76800
#define SM_KHI   102400        // [56][200]
#define SM_VHI   124800        // [64][200]
#define SM_TOTAL 150400

// ---- helpers ----
__device__ __forceinline__ uint32_t smem_u32(const void* p) {
    uint32_t a;
    asm("{ .reg .u64 t; cvta.to.shared.u64 t, %1; cvt.u32.u64 %0, t; }" : "=r"(a) : "l"(p));
    return a;
}
__device__ __forceinline__ void ldm4(uint32_t* r, uint32_t addr) {
    asm volatile("ldmatrix.sync.aligned.m8n8.x4.shared.b16 {%0,%1,%2,%3}, [%4];"
        : "=r"(r[0]), "=r"(r[1]), "=r"(r[2]), "=r"(r[3]) : "r"(addr));
}
__device__ __forceinline__ void ldm2(uint32_t* r, uint32_t addr) {
    asm volatile("ldmatrix.sync.aligned.m8n8.x2.shared.b16 {%0,%1}, [%2];"
        : "=r"(r[0]), "=r"(r[1]) : "r"(addr));
}
__device__ __forceinline__ void ldm2t(uint32_t* r, uint32_t addr) {
    asm volatile("ldmatrix.sync.aligned.m8n8.x2.trans.shared.b16 {%0,%1}, [%2];"
        : "=r"(r[0]), "=r"(r[1]) : "r"(addr));
}
__device__ __forceinline__ void mma16816(float* c, const uint32_t* a, uint2 b) {
    asm volatile("mma.sync.aligned.m16n8k16.row.col.f32.f16.f16.f32 "
        "{%0,%1,%2,%3},{%4,%5,%6,%7},{%8,%9},{%0,%1,%2,%3};"
        : "+f"(c[0]), "+f"(c[1]), "+f"(c[2]), "+f"(c[3])
        : "r"(a[0]), "r"(a[1]), "r"(a[2]), "r"(a[3]), "r"(b.x), "r"(b.y));
}
__device__ __forceinline__ uint32_t hpack(float a, float b) {
    __half2 h = __floats2half2_rn(a, b);
    return *(uint32_t*)&h;
}
__device__ __forceinline__ uint32_t lpack(float a, float b) {
    float ha = __half2float(__float2half_rn(a));
    float hb = __half2float(__float2half_rn(b));
    return hpack(a - ha, b - hb);
}
__device__ __forceinline__ void st_hilo(__half* dh, __half* dl,
                                        int off, float a, float b) {
    *(uint32_t*)(dh + off) = hpack(a, b);
    *(uint32_t*)(dl + off) = lpack(a, b);
}

// ---- pre-packed weight B fragments (fp16, single term) ----
#define NQF (72 * 12 * 32)
#define NPF (24 * 12 * 32)
__device__ uint2 g_bqkv[NQF];
__device__ uint2 g_bproj[NPF];
// combined bias+mask, fp16x2 pairs: [64][6][49][28]
#define CM_N (64 * 6 * 49 * 28)
__device__ uint32_t g_cmask[CM_N];

__global__ void prep_frags(const float* __restrict__ qkv_w,
                           const float* __restrict__ proj_w)
{
    int idx = blockIdx.x * blockDim.x + threadIdx.x;
    if (idx >= NQF + NPF) return;
    const float* W; uint2* dst; int e;
    if (idx < NQF) { e = idx; W = qkv_w; dst = g_bqkv + idx; }
    else { e = idx - NQF; W = proj_w; dst = g_bproj + e; }
    int lane = e & 31, ks = (e >> 5) % 12, nt = (e >> 5) / 12;
    int j = nt * 8 + (lane >> 2);
    int k = ks * 16 + (lane & 3) * 2;
    const float* wr = W + (size_t)j * DIM;
    uint2 v;
    v.x = hpack(wr[k],     wr[k + 1]);
    v.y = hpack(wr[k + 8], wr[k + 9]);
    *dst = v;
}

__global__ void prep_cmask(const int* __restrict__ rpi_raw,
                           const float* __restrict__ mask,
                           const float* __restrict__ rpb)
{
    int idx = blockIdx.x * blockDim.x + threadIdx.x;
    if (idx >= CM_N) return;
    int jp = idx % 28;
    int i  = (idx / 28) % 49;
    int h  = (idx / (28 * 49)) % 6;
    int w  = idx / (28 * 49 * 6);
    bool is64 = (rpi_raw[1] == 0) && (rpi_raw[3] == 0) && (rpi_raw[5] == 0)
             && (rpi_raw[7] == 0) && (rpi_raw[9] == 0);
    float v[2];
    #pragma unroll
    for (int t = 0; t < 2; t++) {
        int j = jp * 2 + t;
        if (j < 49) {
            int e = i * 49 + j;
            int r = is64 ? rpi_raw[2 * e] : rpi_raw[e];
            v[t] = rpb[r * 6 + h] + mask[w * 2401 + e];
        } else v[t] = -30000.f;
    }
    g_cmask[idx] = hpack(v[0], v[1]);
}

// ---- GEMM chunk: 4 m-tiles x NT n-tiles x 12 k-steps ----
// USE_LO: add A_lo * B term (2-term split); else single term.
template <int NT, bool USE_LO>
__device__ __forceinline__ void gemm_chunk(uint32_t aHi, uint32_t aLo,
                                           const uint2* __restrict__ bhi,
                                           float acc[NT][4][4])
{
    #pragma unroll
    for (int n = 0; n < NT; n++)
        #pragma unroll
        for (int m = 0; m < 4; m++)
            #pragma unroll
            for (int q = 0; q < 4; q++) acc[n][m][q] = 0.f;
    #pragma unroll
    for (int ks = 0; ks < 12; ks++) {
        uint2 bh[NT];
        #pragma unroll
        for (int n = 0; n < NT; n++) bh[n] = bhi[(n * 12 + ks) * 32];
        uint32_t ah[4][4], al[4][4];
        #pragma unroll
        for (int m = 0; m < 4; m++) {
            ldm4(ah[m], aHi + m * 6400 + ks * 32);
            if (USE_LO) ldm4(al[m], aLo + m * 6400 + ks * 32);
        }
        #pragma unroll
        for (int n = 0; n < NT; n++)
            #pragma unroll
            for (int m = 0; m < 4; m++) {
                mma16816(acc[n][m], ah[m], bh[n]);
                if (USE_LO) mma16816(acc[n][m], al[m], bh[n]);
            }
    }
}

extern "C" __global__ void __launch_bounds__(THREADS, 1)
win_attn_kernel(const float* __restrict__ x,
                const float* __restrict__ qkv_b,
                const float* __restrict__ proj_b,
                float* __restrict__ out)
{
    extern __shared__ char smem[];
    __half* xhi = (__half*)(smem + SM_XHI);
    __half* xlo = (__half*)(smem + SM_XLO);
    __half* qhi = (__half*)(smem + SM_QHI);
    __half* qlo = (__half*)(smem + SM_QLO);
    __half* khi = (__half*)(smem + SM_KHI);
    __half* vhi = (__half*)(smem + SM_VHI);

    const int tid  = threadIdx.x;
    const int bw   = blockIdx.x;
    const int widx = bw & 63;
    const int lane = tid & 31, warp = tid >> 5;
    const int gid = lane >> 2, tig = lane & 3;
    const uint32_t sb = smem_u32(smem);

    // ldmatrix A-operand lane addressing (validated R7-R9)
    const int rowA = (lane & 7) + ((lane >> 3) & 1) * 8;
    const int colA = (lane >> 4) * 8;
    const uint32_t aHi = sb + SM_XHI + (uint32_t)(rowA * ST + colA) * 2;
    const uint32_t aLo = aHi + (SM_XLO - SM_XHI);

    // ---------------- Phase 1: stage x -> fp16 hi (qkv is 1-term); zero pads ----------------
    {
        // no-div mapping: row = tid & 63, col-group = tid >> 6 (6 groups x 32 cols)
        const int r  = tid & 63;
        const int c0 = (tid >> 6) * 32;
        const bool real = r < NTOK;
        const float* xr = x + (size_t)bw * (NTOK * DIM) + (size_t)r * DIM + c0;
        uint32_t* dh = (uint32_t*)(xhi + r * ST + c0);
        uint32_t* dl = (uint32_t*)(xlo + r * ST + c0);
        #pragma unroll
        for (int c = 0; c < 32; c += 2) {
            float2 v = real ? *(const float2*)(xr + c) : make_float2(0.f, 0.f);
            dh[c >> 1] = hpack(v.x, v.y);
            if (!real) dl[c >> 1] = 0;   // pad rows of xlo must be 0 for proj
        }
        // zero rows 49..63 of q(hi/lo), v(hi); rows 49..55 of k(hi)
        uint32_t* q32h = (uint32_t*)qhi; uint32_t* q32l = (uint32_t*)qlo;
        uint32_t* k32h = (uint32_t*)khi; uint32_t* v32h = (uint32_t*)vhi;
        for (int i = tid; i < 15 * 100; i += THREADS) {
            int rr = 49 + i / 100, cc = i % 100;
            int o = rr * 100 + cc;
            q32h[o] = 0; q32l[o] = 0; v32h[o] = 0;
            if (rr < 56) k32h[o] = 0;
        }
    }
    __syncthreads();

    // ---------------- Phase 2: QKV GEMM (1-term) -> Q (hi/lo), K (hi), V (hi) ----------------
    {
        const int g = warp >> 2;   // 0=Q 1=K 2=V
        __half* dh = (g == 0) ? qhi : (g == 1) ? khi : vhi;
        #pragma unroll 1
        for (int c = 0; c < 2; c++) {
            const int ntbase = warp * 6 + c * 3;
            const uint2* bhi = g_bqkv + (size_t)ntbase * 384 + lane;
            float acc[3][4][4];
            gemm_chunk<3, false>(aHi, aLo, bhi, acc);
            #pragma unroll
            for (int n = 0; n < 3; n++) {
                int col = (ntbase + n) * 8 + tig * 2;
                int cc = col - g * 192;
                float b0 = qkv_b[col], b1 = qkv_b[col + 1];
                #pragma unroll
                for (int m = 0; m < 4; m++) {
                    int r0 = m * 16 + gid;
                    if (r0 < NTOK) {
                        if (g == 0) st_hilo(qhi, qlo, r0 * ST + cc,
                                            acc[n][m][0] + b0, acc[n][m][1] + b1);
                        else *(uint32_t*)(dh + r0 * ST + cc) =
                                 hpack(acc[n][m][0] + b0, acc[n][m][1] + b1);
                    }
                    if (r0 + 8 < NTOK) {
                        if (g == 0) st_hilo(qhi, qlo, (r0 + 8) * ST + cc,
                                            acc[n][m][2] + b0, acc[n][m][3] + b1);
                        else *(uint32_t*)(dh + (r0 + 8) * ST + cc) =
                                 hpack(acc[n][m][2] + b0, acc[n][m][3] + b1);
                    }
                }
            }
        }
    }
    __syncthreads();

    // ---------------- Phase 3: attention via mma (warp = head x row-half) ----------------
    {
        const float scale = 0.17677669529663687f;  // 32^-0.5
        const int h  = warp >> 1;
        const int mh = warp & 1;
        const int qo = h * 32;
        const uint32_t* cm = g_cmask + ((size_t)(widx * 6 + h) * 49) * 28;

        const uint32_t aQh = sb + SM_QHI + (uint32_t)((mh * 32 + rowA) * ST + qo + colA) * 2;
        const uint32_t aQl = aQh + (SM_QLO - SM_QHI);
        const int kr = lane & 7, km = (lane >> 3) & 1;
        const uint32_t bKh = sb + SM_KHI + (uint32_t)(kr * ST + qo + km * 8) * 2;
        const uint32_t bVh = sb + SM_VHI + (uint32_t)((kr + km * 8) * ST + qo) * 2;

        #pragma unroll 1
        for (int m = 0; m < 2; m++) {
            const int i0 = mh * 32 + m * 16 + gid;
            const int i1 = i0 + 8;

            // ---- scores: S = Q K^T (2-term on Q) ----
            float sc[7][4];
            #pragma unroll
            for (int n = 0; n < 7; n++)
                #pragma unroll
                for (int q = 0; q < 4; q++) sc[n][q] = 0.f;
            #pragma unroll
            for (int ks = 0; ks < 2; ks++) {
                uint32_t ah[4], al[4];
                ldm4(ah, aQh + m * 6400 + ks * 32);
                ldm4(al, aQl + m * 6400 + ks * 32);
                #pragma unroll
                for (int n = 0; n < 7; n++) {
                    uint32_t bh[2];
                    ldm2(bh, bKh + n * 3200 + ks * 32);
                    uint2 BH = make_uint2(bh[0], bh[1]);
                    mma16816(sc[n], ah, BH);
                    mma16816(sc[n], al, BH);
                }
            }

            // ---- scale + bias+mask ----
            #pragma unroll
            for (int n = 0; n < 7; n++) {
                if (i0 < NTOK) {
                    uint32_t cp = cm[i0 * 28 + n * 4 + tig];
                    __half2 cf = *(__half2*)&cp;
                    sc[n][0] = sc[n][0] * scale + __half2float(cf.x);
                    sc[n][1] = sc[n][1] * scale + __half2float(cf.y);
                } else { sc[n][0] = -30000.f; sc[n][1] = -30000.f; }
                if (i1 < NTOK) {
                    uint32_t cp = cm[i1 * 28 + n * 4 + tig];
                    __half2 cf = *(__half2*)&cp;
                    sc[n][2] = sc[n][2] * scale + __half2float(cf.x);
                    sc[n][3] = sc[n][3] * scale + __half2float(cf.y);
                } else { sc[n][2] = -30000.f; sc[n][3] = -30000.f; }
            }

            // ---- row softmax (rows i0, i1; reduce across tig via shfl) ----
            float mA = -1e30f, mB = -1e30f;
            #pragma unroll
            for (int n = 0; n < 7; n++) {
                mA = fmaxf(mA, fmaxf(sc[n][0], sc[n][1]));
                mB = fmaxf(mB, fmaxf(sc[n][2], sc[n][3]));
            }
            mA = fmaxf(mA, __shfl_xor_sync(0xffffffffu, mA, 1));
            mA = fmaxf(mA, __shfl_xor_sync(0xffffffffu, mA, 2));
            mB = fmaxf(mB, __shfl_xor_sync(0xffffffffu, mB, 1));
            mB = fmaxf(mB, __shfl_xor_sync(0xffffffffu, mB, 2));
            float sA = 0.f, sB = 0.f;
            #pragma unroll
            for (int n = 0; n < 7; n++) {
                sc[n][0] = __expf(sc[n][0] - mA); sA += sc[n][0];
                sc[n][1] = __expf(sc[n][1] - mA); sA += sc[n][1];
                sc[n][2] = __expf(sc[n][2] - mB); sB += sc[n][2];
                sc[n][3] = __expf(sc[n][3] - mB); sB += sc[n][3];
            }
            sA += __shfl_xor_sync(0xffffffffu, sA, 1);
            sA += __shfl_xor_sync(0xffffffffu, sA, 2);
            sB += __shfl_xor_sync(0xffffffffu, sB, 1);
            sB += __shfl_xor_sync(0xffffffffu, sB, 2);
            float rA = 1.f / sA, rB = 1.f / sB;
            #pragma unroll
            for (int n = 0; n < 7; n++) {
                sc[n][0] *= rA; sc[n][1] *= rA;
                sc[n][2] *= rB; sc[n][3] *= rB;
            }

            // ---- repack P fragments (hi/lo fp16) straight from accumulators ----
            uint32_t ph[4][4], pl[4][4];
            #pragma unroll
            for (int jt = 0; jt < 4; jt++) {
                int nA = 2 * jt, nB = 2 * jt + 1;
                ph[jt][0] = hpack(sc[nA][0], sc[nA][1]);
                pl[jt][0] = lpack(sc[nA][0], sc[nA][1]);
                ph[jt][1] = hpack(sc[nA][2], sc[nA][3]);
                pl[jt][1] = lpack(sc[nA][2], sc[nA][3]);
                if (nB < 7) {
                    ph[jt][2] = hpack(sc[nB][0], sc[nB][1]);
                    pl[jt][2] = lpack(sc[nB][0], sc[nB][1]);
                    ph[jt][3] = hpack(sc[nB][2], sc[nB][3]);
                    pl[jt][3] = lpack(sc[nB][2], sc[nB][3]);
                } else {
                    ph[jt][2] = 0; pl[jt][2] = 0; ph[jt][3] = 0; pl[jt][3] = 0;
                }
            }

            // ---- AV: out = P V (2-term on P), V via ldmatrix.trans ----
            float av[4][4];
            #pragma unroll
            for (int nd = 0; nd < 4; nd++)
                #pragma unroll
                for (int q = 0; q < 4; q++) av[nd][q] = 0.f;
            #pragma unroll
            for (int jt = 0; jt < 4; jt++) {
                #pragma unroll
                for (int nd = 0; nd < 4; nd++) {
                    uint32_t bh[2];
                    ldm2t(bh, bVh + jt * 16 * 400 + nd * 16);
                    uint2 BH = make_uint2(bh[0], bh[1]);
                    mma16816(av[nd], ph[jt], BH);
                    mma16816(av[nd], pl[jt], BH);
                }
            }

            // ---- store AV out as proj A input (fp16 hi/lo into x buffers) ----
            #pragma unroll
            for (int nd = 0; nd < 4; nd++) {
                int col = qo + nd * 8 + tig * 2;
                if (i0 < NTOK) st_hilo(xhi, xlo, i0 * ST + col, av[nd][0], av[nd][1]);
                if (i1 < NTOK) st_hilo(xhi, xlo, i1 * ST + col, av[nd][2], av[nd][3]);
            }
        }
    }
    __syncthreads();

    // ---------------- Phase 4: proj GEMM (2-term) ----------------
    {
        const int ntbase = warp * 2;
        const uint2* bhi = g_bproj + (size_t)ntbase * 384 + lane;
        float acc[2][4][4];
        gemm_chunk<2, true>(aHi, aLo, bhi, acc);
        float* og = out + (size_t)bw * (NTOK * DIM);
        #pragma unroll
        for (int n = 0; n < 2; n++) {
            int col = (ntbase + n) * 8 + tig * 2;
            float b0 = proj_b[col], b1 = proj_b[col + 1];
            #pragma unroll
            for (int m = 0; m < 4; m++) {
                int r0 = m * 16 + gid;
                if (r0 < NTOK)
                    *(float2*)(og + r0 * DIM + col) =
                        make_float2(acc[n][m][0] + b0, acc[n][m][1] + b1);
                if (r0 + 8 < NTOK)
                    *(float2*)(og + (r0 + 8) * DIM + col) =
                        make_float2(acc[n][m][2] + b0, acc[n][m][3] + b1);
            }
        }
    }
}

extern "C" void kernel_launch(void* const* d_in, const int* in_sizes, int n_in,
                              void* d_out, int out_size)
{
    const float* x      = (const float*)d_in[0];
    const int*   rpi    = (const int*)d_in[1];
    const float* mask   = (const float*)d_in[2];
    const float* qkv_w  = (const float*)d_in[3];
    const float* qkv_b  = (const float*)d_in[4];
    const float* proj_w = (const float*)d_in[5];
    const float* proj_b = (const float*)d_in[6];
    const float* rpb    = (const float*)d_in[7];

    prep_frags<<<(NQF + NPF + 255) / 256, 256>>>(qkv_w, proj_w);
    prep_cmask<<<(CM_N + 255) / 256, 256>>>(rpi, mask, rpb);

    cudaFuncSetAttribute(win_attn_kernel,
                         cudaFuncAttributeMaxDynamicSharedMemorySize, SM_TOTAL);
    win_attn_kernel<<<4096, THREADS, SM_TOTAL>>>(x, qkv_b, proj_b, (float*)d_out);
}

// round 11
// speedup vs baseline: 11.0936x; 1.1197x over previous
#include <cuda_runtime.h>
#include <cuda_fp16.h>
#include <cstdint>

#define HEADS 6
#define DIM 192
#define NTOK 49
#define THREADS 384
#define ST 200                 // fp16 row stride (400B)

// smem byte offsets
#define SM_XHI   0             // [64][200] fp16 (x, later AV out = proj A)
#define SM_QHI   25600         // [64][200] (Q pre-scaled by 32^-0.5)
#define SM_KHI   51200         // [56][200]
#define SM_VHI   73600         // [64][200]
#define SM_TOTAL 99200

// ---- helpers ----
__device__ __forceinline__ uint32_t smem_u32(const void* p) {
    uint32_t a;
    asm("{ .reg .u64 t; cvta.to.shared.u64 t, %1; cvt.u32.u64 %0, t; }" : "=r"(a) : "l"(p));
    return a;
}
__device__ __forceinline__ void ldm4(uint32_t* r, uint32_t addr) {
    asm volatile("ldmatrix.sync.aligned.m8n8.x4.shared.b16 {%0,%1,%2,%3}, [%4];"
        : "=r"(r[0]), "=r"(r[1]), "=r"(r[2]), "=r"(r[3]) : "r"(addr));
}
__device__ __forceinline__ void ldm2(uint32_t* r, uint32_t addr) {
    asm volatile("ldmatrix.sync.aligned.m8n8.x2.shared.b16 {%0,%1}, [%2];"
        : "=r"(r[0]), "=r"(r[1]) : "r"(addr));
}
__device__ __forceinline__ void ldm2t(uint32_t* r, uint32_t addr) {
    asm volatile("ldmatrix.sync.aligned.m8n8.x2.trans.shared.b16 {%0,%1}, [%2];"
        : "=r"(r[0]), "=r"(r[1]) : "r"(addr));
}
__device__ __forceinline__ void mma16816(float* c, const uint32_t* a, uint2 b) {
    asm volatile("mma.sync.aligned.m16n8k16.row.col.f32.f16.f16.f32 "
        "{%0,%1,%2,%3},{%4,%5,%6,%7},{%8,%9},{%0,%1,%2,%3};"
        : "+f"(c[0]), "+f"(c[1]), "+f"(c[2]), "+f"(c[3])
        : "r"(a[0]), "r"(a[1]), "r"(a[2]), "r"(a[3]), "r"(b.x), "r"(b.y));
}
__device__ __forceinline__ uint32_t hpack(float a, float b) {
    __half2 h = __floats2half2_rn(a, b);
    return *(uint32_t*)&h;
}
__device__ __forceinline__ uint32_t lpack(float a, float b) {
    float ha = __half2float(__float2half_rn(a));
    float hb = __half2float(__float2half_rn(b));
    return hpack(a - ha, b - hb);
}

// ---- pre-packed weight B fragments (fp16, single term) ----
#define NQF (72 * 12 * 32)
#define NPF (24 * 12 * 32)
__device__ uint2 g_bqkv[NQF];
__device__ uint2 g_bproj[NPF];
// combined bias+mask, fp16x2 pairs: [64][6][49][28]
#define CM_N (64 * 6 * 49 * 28)
__device__ uint32_t g_cmask[CM_N];

__global__ void prep_frags(const float* __restrict__ qkv_w,
                           const float* __restrict__ proj_w)
{
    int idx = blockIdx.x * blockDim.x + threadIdx.x;
    if (idx >= NQF + NPF) return;
    const float* W; uint2* dst; int e;
    if (idx < NQF) { e = idx; W = qkv_w; dst = g_bqkv + idx; }
    else { e = idx - NQF; W = proj_w; dst = g_bproj + e; }
    int lane = e & 31, ks = (e >> 5) % 12, nt = (e >> 5) / 12;
    int j = nt * 8 + (lane >> 2);
    int k = ks * 16 + (lane & 3) * 2;
    const float* wr = W + (size_t)j * DIM;
    uint2 v;
    v.x = hpack(wr[k],     wr[k + 1]);
    v.y = hpack(wr[k + 8], wr[k + 9]);
    *dst = v;
}

__global__ void prep_cmask(const int* __restrict__ rpi_raw,
                           const float* __restrict__ mask,
                           const float* __restrict__ rpb)
{
    int idx = blockIdx.x * blockDim.x + threadIdx.x;
    if (idx >= CM_N) return;
    int jp = idx % 28;
    int i  = (idx / 28) % 49;
    int h  = (idx / (28 * 49)) % 6;
    int w  = idx / (28 * 49 * 6);
    bool is64 = (rpi_raw[1] == 0) && (rpi_raw[3] == 0) && (rpi_raw[5] == 0)
             && (rpi_raw[7] == 0) && (rpi_raw[9] == 0);
    float v[2];
    #pragma unroll
    for (int t = 0; t < 2; t++) {
        int j = jp * 2 + t;
        if (j < 49) {
            int e = i * 49 + j;
            int r = is64 ? rpi_raw[2 * e] : rpi_raw[e];
            v[t] = rpb[r * 6 + h] + mask[w * 2401 + e];
        } else v[t] = -30000.f;
    }
    g_cmask[idx] = hpack(v[0], v[1]);
}

// ---- GEMM chunk: 4 m-tiles x NT n-tiles x 12 k-steps, single-term fp16 ----
template <int NT>
__device__ __forceinline__ void gemm_chunk(uint32_t aHi,
                                           const uint2* __restrict__ bhi,
                                           float acc[NT][4][4])
{
    #pragma unroll
    for (int n = 0; n < NT; n++)
        #pragma unroll
        for (int m = 0; m < 4; m++)
            #pragma unroll
            for (int q = 0; q < 4; q++) acc[n][m][q] = 0.f;
    #pragma unroll
    for (int ks = 0; ks < 12; ks++) {
        uint2 bh[NT];
        #pragma unroll
        for (int n = 0; n < NT; n++) bh[n] = bhi[(n * 12 + ks) * 32];
        uint32_t ah[4][4];
        #pragma unroll
        for (int m = 0; m < 4; m++)
            ldm4(ah[m], aHi + m * 6400 + ks * 32);
        #pragma unroll
        for (int n = 0; n < NT; n++)
            #pragma unroll
            for (int m = 0; m < 4; m++)
                mma16816(acc[n][m], ah[m], bh[n]);
    }
}

extern "C" __global__ void __launch_bounds__(THREADS, 1)
win_attn_kernel(const float* __restrict__ x,
                const float* __restrict__ qkv_b,
                const float* __restrict__ proj_b,
                float* __restrict__ out)
{
    extern __shared__ char smem[];
    __half* xhi = (__half*)(smem + SM_XHI);
    __half* qhi = (__half*)(smem + SM_QHI);
    __half* khi = (__half*)(smem + SM_KHI);
    __half* vhi = (__half*)(smem + SM_VHI);

    const int tid  = threadIdx.x;
    const int bw   = blockIdx.x;
    const int widx = bw & 63;
    const int lane = tid & 31, warp = tid >> 5;
    const int gid = lane >> 2, tig = lane & 3;
    const uint32_t sb = smem_u32(smem);

    // ldmatrix A-operand lane addressing (validated R7-R10)
    const int rowA = (lane & 7) + ((lane >> 3) & 1) * 8;
    const int colA = (lane >> 4) * 8;
    const uint32_t aHi = sb + SM_XHI + (uint32_t)(rowA * ST + colA) * 2;

    // ---------------- Phase 1: stage x -> fp16; zero pads ----------------
    {
        const int r  = tid & 63;
        const int c0 = (tid >> 6) * 32;
        const bool real = r < NTOK;
        const float* xr = x + (size_t)bw * (NTOK * DIM) + (size_t)r * DIM + c0;
        uint32_t* dh = (uint32_t*)(xhi + r * ST + c0);
        #pragma unroll
        for (int c = 0; c < 32; c += 2) {
            float2 v = real ? *(const float2*)(xr + c) : make_float2(0.f, 0.f);
            dh[c >> 1] = hpack(v.x, v.y);
        }
        // zero rows 49..63 of q, v; rows 49..55 of k
        uint32_t* q32 = (uint32_t*)qhi;
        uint32_t* k32 = (uint32_t*)khi;
        uint32_t* v32 = (uint32_t*)vhi;
        for (int i = tid; i < 15 * 100; i += THREADS) {
            int rr = 49 + i / 100, cc = i % 100;
            int o = rr * 100 + cc;
            q32[o] = 0; v32[o] = 0;
            if (rr < 56) k32[o] = 0;
        }
    }
    __syncthreads();

    // ---------------- Phase 2: QKV GEMM (1-term) -> Q(pre-scaled), K, V ----------------
    {
        const float scale = 0.17677669529663687f;  // 32^-0.5, folded into Q
        const int g = warp >> 2;   // 0=Q 1=K 2=V
        __half* dh = (g == 0) ? qhi : (g == 1) ? khi : vhi;
        const float smul = (g == 0) ? scale : 1.f;
        #pragma unroll 1
        for (int c = 0; c < 2; c++) {
            const int ntbase = warp * 6 + c * 3;
            const uint2* bhi = g_bqkv + (size_t)ntbase * 384 + lane;
            float acc[3][4][4];
            gemm_chunk<3>(aHi, bhi, acc);
            #pragma unroll
            for (int n = 0; n < 3; n++) {
                int col = (ntbase + n) * 8 + tig * 2;
                int cc = col - g * 192;
                float b0 = qkv_b[col], b1 = qkv_b[col + 1];
                #pragma unroll
                for (int m = 0; m < 4; m++) {
                    int r0 = m * 16 + gid;
                    if (r0 < NTOK)
                        *(uint32_t*)(dh + r0 * ST + cc) =
                            hpack(smul * (acc[n][m][0] + b0), smul * (acc[n][m][1] + b1));
                    if (r0 + 8 < NTOK)
                        *(uint32_t*)(dh + (r0 + 8) * ST + cc) =
                            hpack(smul * (acc[n][m][2] + b0), smul * (acc[n][m][3] + b1));
                }
            }
        }
    }
    __syncthreads();

    // ---------------- Phase 3: attention via mma (warp = head x row-half) ----------------
    {
        const int h  = warp >> 1;
        const int mh = warp & 1;
        const int qo = h * 32;
        const uint32_t* cm = g_cmask + ((size_t)(widx * 6 + h) * 49) * 28;

        const uint32_t aQh = sb + SM_QHI + (uint32_t)((mh * 32 + rowA) * ST + qo + colA) * 2;
        const int kr = lane & 7, km = (lane >> 3) & 1;
        const uint32_t bKh = sb + SM_KHI + (uint32_t)(kr * ST + qo + km * 8) * 2;
        const uint32_t bVh = sb + SM_VHI + (uint32_t)((kr + km * 8) * ST + qo) * 2;

        #pragma unroll 1
        for (int m = 0; m < 2; m++) {
            const int i0 = mh * 32 + m * 16 + gid;
            const int i1 = i0 + 8;

            // ---- scores: S = Q K^T (1-term; Q pre-scaled) ----
            float sc[7][4];
            #pragma unroll
            for (int n = 0; n < 7; n++)
                #pragma unroll
                for (int q = 0; q < 4; q++) sc[n][q] = 0.f;
            #pragma unroll
            for (int ks = 0; ks < 2; ks++) {
                uint32_t ah[4];
                ldm4(ah, aQh + m * 6400 + ks * 32);
                #pragma unroll
                for (int n = 0; n < 7; n++) {
                    uint32_t bh[2];
                    ldm2(bh, bKh + n * 3200 + ks * 32);
                    uint2 BH = make_uint2(bh[0], bh[1]);
                    mma16816(sc[n], ah, BH);
                }
            }

            // ---- + bias+mask (scale already folded into Q) ----
            #pragma unroll
            for (int n = 0; n < 7; n++) {
                if (i0 < NTOK) {
                    uint32_t cp = cm[i0 * 28 + n * 4 + tig];
                    __half2 cf = *(__half2*)&cp;
                    sc[n][0] += __half2float(cf.x);
                    sc[n][1] += __half2float(cf.y);
                } else { sc[n][0] = -30000.f; sc[n][1] = -30000.f; }
                if (i1 < NTOK) {
                    uint32_t cp = cm[i1 * 28 + n * 4 + tig];
                    __half2 cf = *(__half2*)&cp;
                    sc[n][2] += __half2float(cf.x);
                    sc[n][3] += __half2float(cf.y);
                } else { sc[n][2] = -30000.f; sc[n][3] = -30000.f; }
            }

            // ---- row softmax (rows i0, i1; reduce across tig via shfl) ----
            float mA = -1e30f, mB = -1e30f;
            #pragma unroll
            for (int n = 0; n < 7; n++) {
                mA = fmaxf(mA, fmaxf(sc[n][0], sc[n][1]));
                mB = fmaxf(mB, fmaxf(sc[n][2], sc[n][3]));
            }
            mA = fmaxf(mA, __shfl_xor_sync(0xffffffffu, mA, 1));
            mA = fmaxf(mA, __shfl_xor_sync(0xffffffffu, mA, 2));
            mB = fmaxf(mB, __shfl_xor_sync(0xffffffffu, mB, 1));
            mB = fmaxf(mB, __shfl_xor_sync(0xffffffffu, mB, 2));
            float sA = 0.f, sB = 0.f;
            #pragma unroll
            for (int n = 0; n < 7; n++) {
                sc[n][0] = __expf(sc[n][0] - mA); sA += sc[n][0];
                sc[n][1] = __expf(sc[n][1] - mA); sA += sc[n][1];
                sc[n][2] = __expf(sc[n][2] - mB); sB += sc[n][2];
                sc[n][3] = __expf(sc[n][3] - mB); sB += sc[n][3];
            }
            sA += __shfl_xor_sync(0xffffffffu, sA, 1);
            sA += __shfl_xor_sync(0xffffffffu, sA, 2);
            sB += __shfl_xor_sync(0xffffffffu, sB, 1);
            sB += __shfl_xor_sync(0xffffffffu, sB, 2);
            float rA = 1.f / sA, rB = 1.f / sB;
            #pragma unroll
            for (int n = 0; n < 7; n++) {
                sc[n][0] *= rA; sc[n][1] *= rA;
                sc[n][2] *= rB; sc[n][3] *= rB;
            }

            // ---- repack P fragments (hi/lo fp16, registers only) ----
            uint32_t ph[4][4], pl[4][4];
            #pragma unroll
            for (int jt = 0; jt < 4; jt++) {
                int nA = 2 * jt, nB = 2 * jt + 1;
                ph[jt][0] = hpack(sc[nA][0], sc[nA][1]);
                pl[jt][0] = lpack(sc[nA][0], sc[nA][1]);
                ph[jt][1] = hpack(sc[nA][2], sc[nA][3]);
                pl[jt][1] = lpack(sc[nA][2], sc[nA][3]);
                if (nB < 7) {
                    ph[jt][2] = hpack(sc[nB][0], sc[nB][1]);
                    pl[jt][2] = lpack(sc[nB][0], sc[nB][1]);
                    ph[jt][3] = hpack(sc[nB][2], sc[nB][3]);
                    pl[jt][3] = lpack(sc[nB][2], sc[nB][3]);
                } else {
                    ph[jt][2] = 0; pl[jt][2] = 0; ph[jt][3] = 0; pl[jt][3] = 0;
                }
            }

            // ---- AV: out = P V (2-term on P), V via ldmatrix.trans ----
            float av[4][4];
            #pragma unroll
            for (int nd = 0; nd < 4; nd++)
                #pragma unroll
                for (int q = 0; q < 4; q++) av[nd][q] = 0.f;
            #pragma unroll
            for (int jt = 0; jt < 4; jt++) {
                #pragma unroll
                for (int nd = 0; nd < 4; nd++) {
                    uint32_t bh[2];
                    ldm2t(bh, bVh + jt * 16 * 400 + nd * 16);
                    uint2 BH = make_uint2(bh[0], bh[1]);
                    mma16816(av[nd], ph[jt], BH);
                    mma16816(av[nd], pl[jt], BH);
                }
            }

            // ---- store AV out (single fp16) as proj A input ----
            #pragma unroll
            for (int nd = 0; nd < 4; nd++) {
                int col = qo + nd * 8 + tig * 2;
                if (i0 < NTOK)
                    *(uint32_t*)(xhi + i0 * ST + col) = hpack(av[nd][0], av[nd][1]);
                if (i1 < NTOK)
                    *(uint32_t*)(xhi + i1 * ST + col) = hpack(av[nd][2], av[nd][3]);
            }
        }
    }
    __syncthreads();

    // ---------------- Phase 4: proj GEMM (1-term) ----------------
    {
        const int ntbase = warp * 2;
        const uint2* bhi = g_bproj + (size_t)ntbase * 384 + lane;
        float acc[2][4][4];
        gemm_chunk<2>(aHi, bhi, acc);
        float* og = out + (size_t)bw * (NTOK * DIM);
        #pragma unroll
        for (int n = 0; n < 2; n++) {
            int col = (ntbase + n) * 8 + tig * 2;
            float b0 = proj_b[col], b1 = proj_b[col + 1];
            #pragma unroll
            for (int m = 0; m < 4; m++) {
                int r0 = m * 16 + gid;
                if (r0 < NTOK)
                    *(float2*)(og + r0 * DIM + col) =
                        make_float2(acc[n][m][0] + b0, acc[n][m][1] + b1);
                if (r0 + 8 < NTOK)
                    *(float2*)(og + (r0 + 8) * DIM + col) =
                        make_float2(acc[n][m][2] + b0, acc[n][m][3] + b1);
            }
        }
    }
}

extern "C" void kernel_launch(void* const* d_in, const int* in_sizes, int n_in,
                              void* d_out, int out_size)
{
    const float* x      = (const float*)d_in[0];
    const int*   rpi    = (const int*)d_in[1];
    const float* mask   = (const float*)d_in[2];
    const float* qkv_w  = (const float*)d_in[3];
    const float* qkv_b  = (const float*)d_in[4];
    const float* proj_w = (const float*)d_in[5];
    const float* proj_b = (const float*)d_in[6];
    const float* rpb    = (const float*)d_in[7];

    prep_frags<<<(NQF + NPF + 255) / 256, 256>>>(qkv_w, proj_w);
    prep_cmask<<<(CM_N + 255) / 256, 256>>>(rpi, mask, rpb);

    cudaFuncSetAttribute(win_attn_kernel,
                         cudaFuncAttributeMaxDynamicSharedMemorySize, SM_TOTAL);
    win_attn_kernel<<<4096, THREADS, SM_TOTAL>>>(x, qkv_b, proj_b, (float*)d_out);
}